// round 4
// baseline (speedup 1.0000x reference)
#include <cuda_runtime.h>
#include <math.h>

// ---------------------------------------------------------------------------
// StyleGAN2 up-2x synthesis layer, restructured:
//   Stage 0: per-cout L2-normalize + spatially flip weights -> g_wt[tap][cin][co]
//   Stage 1: parity-decomposed channel-mix conv: z = wf (*) upsample2(x)
//            z stored padded [8][256][132][136] fp32 (only [0,131) read later)
//   Stage 2: 4x4 FIR (separable [1,3,3,1]/4 per axis) + noise + bias + lrelu*sqrt2
// ---------------------------------------------------------------------------

#define CK 16   // cin chunk for stage-1 shared-memory tiling

__device__ float g_wt[9 * 512 * 256];                      // [tap(ty*3+tx)][cin][co]
__device__ float g_z[(size_t)8 * 256 * 132 * 136];         // [b][co][132][136]

// ---------------------------- Stage 0: weight prep -------------------------
__global__ void prep_weights(const float* __restrict__ w) {
    int co  = blockIdx.x;           // 256 blocks
    int tid = threadIdx.x;          // 256 threads
    const float* wc = w + (size_t)co * 4608;   // [512][3][3]

    float s = 0.f;
    for (int i = tid; i < 4608; i += 256) { float v = wc[i]; s += v * v; }
    __shared__ float red[256];
    red[tid] = s;
    __syncthreads();
    for (int off = 128; off > 0; off >>= 1) {
        if (tid < off) red[tid] += red[tid + off];
        __syncthreads();
    }
    float inv = rsqrtf(red[0] + 1e-8f);

    // wf[ty][tx] = w[co][cin][2-ty][2-tx] * inv  (flipped, normalized)
    for (int i = tid; i < 4608; i += 256) {
        int cin = i / 9, r = i % 9;
        int ty = r / 3, tx = r % 3;
        float v = wc[cin * 9 + (2 - ty) * 3 + (2 - tx)] * inv;
        g_wt[(size_t)r * (512 * 256) + cin * 256 + co] = v;
    }
}

// ---------------------------- Stage 1: parity conv -------------------------
// grid: (81 tiles (9x9 over p in [0,72)), 8 co-tiles of 32, 8 batches), 256 thr
// thread: co_l = tid&31, patch(2py x 4px) = tid>>5. 32 fp32 accumulators:
//   acc[parity(ey*2+ex)][dy][dx]
__global__ __launch_bounds__(256) void stage1(const float* __restrict__ x) {
    int tile = blockIdx.x;
    int tly = tile / 9, tlx = tile % 9;
    int p0y = tly * 8, p0x = tlx * 8;
    int co0 = blockIdx.y * 32;
    int b   = blockIdx.z;
    int tid = threadIdx.x;
    int co_l  = tid & 31;
    int patch = tid >> 5;                 // 0..7
    int py0 = (patch >> 1) * 2;           // 0,2,4,6
    int px0 = (patch & 1) * 4;            // 0,4

    // shared: phase A: xs[CK][9][12] (1728 f) + ws[9][CK][32] (4608 f)
    //         phase B: zstage[32][257] (8224 f)  -- aliased
    __shared__ __align__(16) float smbuf[8224];
    float (*xs)[9][12]  = (float (*)[9][12])smbuf;
    float (*ws)[CK][32] = (float (*)[CK][32])(smbuf + CK * 108);

    float acc[4][2][4];
#pragma unroll
    for (int p = 0; p < 4; p++)
#pragma unroll
        for (int i = 0; i < 2; i++)
#pragma unroll
            for (int j = 0; j < 4; j++) acc[p][i][j] = 0.f;

    const float* xb = x + (size_t)b * 512 * 4096;

    for (int c0 = 0; c0 < 512; c0 += CK) {
        __syncthreads();
        // load x halo tile: xs[c][j][i] = x[b][c0+c][p0y-1+j][p0x-1+i] (0 if OOR)
        for (int idx = tid; idx < CK * 81; idx += 256) {
            int c = idx / 81, r = idx % 81;
            int j = r / 9, i = r % 9;
            int gy = p0y - 1 + j, gx = p0x - 1 + i;
            float v = 0.f;
            if ((unsigned)gy < 64u && (unsigned)gx < 64u)
                v = xb[(size_t)(c0 + c) * 4096 + gy * 64 + gx];
            xs[c][j][i] = v;
        }
        // load weights: ws[tap][c][co]
        for (int idx = tid; idx < 9 * CK * 32; idx += 256) {
            int tap = idx / (CK * 32);
            int rem = idx % (CK * 32);
            int c = rem >> 5, co = rem & 31;
            ws[tap][c][co] =
                g_wt[(size_t)tap * (512 * 256) + (c0 + c) * 256 + co0 + co];
        }
        __syncthreads();

#pragma unroll
        for (int c = 0; c < CK; c++) {
            float wv[9];
#pragma unroll
            for (int k = 0; k < 9; k++) wv[k] = ws[k][c][co_l];
            float xv[3][5];
#pragma unroll
            for (int j = 0; j < 3; j++) {
                float4 v4 = *(const float4*)&xs[c][py0 + j][px0];
                xv[j][0] = v4.x; xv[j][1] = v4.y;
                xv[j][2] = v4.z; xv[j][3] = v4.w;
                xv[j][4] = xs[c][py0 + j][px0 + 4];
            }
#pragma unroll
            for (int dy = 0; dy < 2; dy++) {
#pragma unroll
                for (int dx = 0; dx < 4; dx++) {
                    float xmm = xv[dy][dx];       // x[p-1, q-1]
                    float xm0 = xv[dy][dx + 1];   // x[p-1, q  ]
                    float x0m = xv[dy + 1][dx];   // x[p  , q-1]
                    float x00 = xv[dy + 1][dx + 1];
                    acc[0][dy][dx] += wv[4] * xmm;                     // z[2p ,2q ]
                    acc[1][dy][dx] += wv[3] * xmm + wv[5] * xm0;       // z[2p ,2q+1]
                    acc[2][dy][dx] += wv[1] * xmm + wv[7] * x0m;       // z[2p+1,2q ]
                    acc[3][dy][dx] += wv[0] * xmm + wv[2] * xm0
                                    + wv[6] * x0m + wv[8] * x00;       // z[2p+1,2q+1]
                }
            }
        }
    }

    // --------- transpose through smem for coalesced global stores ----------
    __syncthreads();
    float* zstage = smbuf;                 // [co(32)][257] padded
#pragma unroll
    for (int ey = 0; ey < 2; ey++)
#pragma unroll
        for (int dy = 0; dy < 2; dy++)
#pragma unroll
            for (int ex = 0; ex < 2; ex++)
#pragma unroll
                for (int dx = 0; dx < 4; dx++) {
                    int ny = 2 * (py0 + dy) + ey;
                    int nx = 2 * (px0 + dx) + ex;
                    zstage[co_l * 257 + ny * 16 + nx] = acc[ey * 2 + ex][dy][dx];
                }
    __syncthreads();

    float* zb = g_z + (size_t)(b * 256 + co0) * (132 * 136);
#pragma unroll
    for (int s = 0; s < 32; s++) {
        int flat = s * 256 + tid;
        int cx = flat & 15;
        int r  = (flat >> 4) & 15;
        int co = flat >> 8;
        if (p0y + (r >> 1) < 66 && p0x + (cx >> 1) < 66) {
            int Ny = 2 * p0y + r, Nx = 2 * p0x + cx;
            zb[(size_t)co * (132 * 136) + Ny * 136 + Nx] =
                zstage[co * 257 + r * 16 + cx];
        }
    }
}

// ---------------------------- Stage 2: FIR + epilogue ----------------------
// grid: (16 tiles of 32x32, 256 co, 8 b), 256 threads, 4 px/thread
__global__ __launch_bounds__(256) void stage2(const float* __restrict__ bias,
                                              const float* __restrict__ noise,
                                              const float* __restrict__ nstr,
                                              float* __restrict__ out) {
    int bx  = blockIdx.x;
    int my0 = (bx >> 2) * 32, mx0 = (bx & 3) * 32;
    int co  = blockIdx.y, b = blockIdx.z;
    int tid = threadIdx.x;

    __shared__ float zs[35][36];
    const float* zp = g_z + (size_t)(b * 256 + co) * (132 * 136);
    for (int idx = tid; idx < 35 * 35; idx += 256) {
        int r = idx / 35, c = idx % 35;
        zs[r][c] = zp[(my0 + r) * 136 + mx0 + c];   // reads stay < 132 rows/cols
    }
    __syncthreads();

    float ns = *nstr;
    float bv = bias[co];
    const float c4[4] = {0.25f, 0.75f, 0.75f, 0.25f};  // [1,3,3,1]/4 per axis
    float* op = out + ((size_t)(b * 256 + co) * 128 + my0) * 128 + mx0;

#pragma unroll
    for (int k = 0; k < 4; k++) {
        int pid = k * 256 + tid;
        int py = pid >> 5, px = pid & 31;
        float s = 0.f;
#pragma unroll
        for (int ky = 0; ky < 4; ky++) {
            float t = 0.f;
#pragma unroll
            for (int kx = 0; kx < 4; kx++) t += c4[kx] * zs[py + ky][px + kx];
            s += c4[ky] * t;
        }
        s += noise[(my0 + py) * 128 + mx0 + px] * ns + bv;
        s = (s >= 0.f ? s : 0.2f * s) * 1.41421356237309515f;
        op[py * 128 + px] = s;
    }
}

// ---------------------------------------------------------------------------
extern "C" void kernel_launch(void* const* d_in, const int* in_sizes, int n_in,
                              void* d_out, int out_size) {
    (void)in_sizes; (void)n_in; (void)out_size;
    const float* x     = (const float*)d_in[0];   // [8,512,64,64]
    const float* w     = (const float*)d_in[1];   // [256,512,3,3]
    const float* bias  = (const float*)d_in[2];   // [256]
    const float* noise = (const float*)d_in[3];   // [128,128]
    const float* nstr  = (const float*)d_in[4];   // scalar
    float* out = (float*)d_out;                   // [8,256,128,128]

    prep_weights<<<256, 256>>>(w);

    dim3 g1(81, 8, 8);       // 9x9 spatial tiles (p in [0,72)), 8 co-tiles, 8 b
    stage1<<<g1, 256>>>(x);

    dim3 g2(16, 256, 8);
    stage2<<<g2, 256>>>(bias, noise, nstr, out);
}

// round 6
// speedup vs baseline: 2.4218x; 2.4218x over previous
#include <cuda_runtime.h>
#include <cuda_fp16.h>
#include <stdint.h>
#include <math.h>

// ---------------------------------------------------------------------------
// StyleGAN2 up-2x synthesis layer, tensor-core restructure:
//   Stage 0: per-cout L2-normalize + flip -> g_whh[tap][co][cin] (fp16)
//   Stage 1: 4 parity-plane GEMMs via mma.sync m16n8k16 (fp16 in, fp32 acc)
//            z parity planes stored [b][co][parity][68][72] fp32
//   Stage 2: recompose + 4x4 separable FIR + noise + bias + lrelu*sqrt2
// ---------------------------------------------------------------------------

__device__ __half g_whh[9 * 256 * 512];                        // [tap][co][cin]
__device__ float  g_zp[(size_t)8 * 256 * 4 * 68 * 72];         // [b][co][par][68][72]

__constant__ int c_ntap[4]     = {1, 2, 2, 4};
__constant__ int c_tapid[4][4] = {{4,0,0,0},{3,5,0,0},{1,7,0,0},{0,2,6,8}};
__constant__ int c_tdy[4][4]   = {{0,0,0,0},{0,0,0,0},{0,1,0,0},{0,0,1,1}};
__constant__ int c_tdx[4][4]   = {{0,0,0,0},{0,1,0,0},{0,0,0,0},{0,1,0,1}};

// ---------------------------- Stage 0: weight prep -------------------------
__global__ void prep_weights(const float* __restrict__ w) {
    int co  = blockIdx.x;           // 256 blocks
    int tid = threadIdx.x;          // 256 threads
    const float* wc = w + (size_t)co * 4608;   // [512][3][3]

    float s = 0.f;
    for (int i = tid; i < 4608; i += 256) { float v = wc[i]; s += v * v; }
    __shared__ float red[256];
    red[tid] = s;
    __syncthreads();
    for (int off = 128; off > 0; off >>= 1) {
        if (tid < off) red[tid] += red[tid + off];
        __syncthreads();
    }
    float inv = rsqrtf(red[0] + 1e-8f);

    // g_whh[tap][co][cin] = flipped, normalized weight, fp16
    for (int i = tid; i < 4608; i += 256) {
        int cin = i / 9, r = i % 9;
        int ty = r / 3, tx = r % 3;
        float v = wc[cin * 9 + (2 - ty) * 3 + (2 - tx)] * inv;
        g_whh[((size_t)r * 256 + co) * 512 + cin] = __float2half_rn(v);
    }
}

// ---------------------------- Stage 1: parity GEMMs ------------------------
// grid (85 = 17 row-tiles x 5 col-tiles, 4 parity, 8 b), 256 threads.
// CTA tile: M = 64 spatial (4 rows x 16 cols of a 66x66 parity plane),
//           N = 256 co. Warp: M=32 (2 rows), N=64. K-chunks of 16 cin.
#define KC 16
#define XPAD 24   // halves per (yy,xx) cell: conflict-free A-fragment LDS

__device__ __forceinline__ void mma16816(float* d, const uint32_t* A,
                                         uint32_t b0, uint32_t b1) {
    asm volatile(
        "mma.sync.aligned.m16n8k16.row.col.f32.f16.f16.f32 "
        "{%0,%1,%2,%3}, {%4,%5,%6,%7}, {%8,%9}, {%0,%1,%2,%3};\n"
        : "+f"(d[0]), "+f"(d[1]), "+f"(d[2]), "+f"(d[3])
        : "r"(A[0]), "r"(A[1]), "r"(A[2]), "r"(A[3]), "r"(b0), "r"(b1));
}

__global__ __launch_bounds__(256, 1) void stage1(const float* __restrict__ x) {
    __shared__ __align__(16) __half xs[5 * 17 * XPAD];   // [yy][xx][c]
    __shared__ __align__(16) __half ws[4 * 256 * KC];    // [tap][co][c]

    int bx = blockIdx.x;
    int tr = bx / 5, tc = bx % 5;
    int p0 = (tr == 16) ? 62 : tr * 4;     // rows {0,4,...,60,62} cover [0,66)
    int q0 = (tc == 4)  ? 50 : tc * 16;    // cols {0,16,32,48,50} cover [0,66)
    int par = blockIdx.y, b = blockIdx.z;
    int ntap = c_ntap[par];

    int tid = threadIdx.x, lane = tid & 31, wid = tid >> 5;
    int warp_m = wid & 1, warp_n = wid >> 1;
    int tig = lane & 3, grp = lane >> 2;
    int nb = warp_n * 64;

    float acc[2][8][4];
#pragma unroll
    for (int i = 0; i < 2; i++)
#pragma unroll
        for (int j = 0; j < 8; j++)
#pragma unroll
            for (int k = 0; k < 4; k++) acc[i][j][k] = 0.f;

    const float* xb = x + (size_t)b * 512 * 4096;

    for (int c0 = 0; c0 < 512; c0 += KC) {
        __syncthreads();
        // ---- fill xs[yy][xx][c] = x[b][c0+c][p0-1+yy][q0-1+xx] (fp16, 0 OOB)
        for (int idx = tid; idx < KC * 85; idx += 256) {
            int c = idx / 85, rem = idx % 85;
            int yy = rem / 17, xx = rem % 17;
            int gy = p0 - 1 + yy, gx = q0 - 1 + xx;
            float v = 0.f;
            if ((unsigned)gy < 64u && (unsigned)gx < 64u)
                v = xb[(size_t)(c0 + c) * 4096 + gy * 64 + gx];
            xs[(yy * 17 + xx) * XPAD + c] = __float2half_rn(v);
        }
        // ---- fill ws[ti][co][c] from g_whh[tapid][co][c0..c0+15]
        for (int ti = 0; ti < ntap; ti++) {
            const uint32_t* src =
                (const uint32_t*)&g_whh[(size_t)c_tapid[par][ti] * 256 * 512 + c0];
            uint32_t* dst = (uint32_t*)&ws[ti * 256 * KC];
            for (int idx = tid; idx < 2048; idx += 256) {
                int co = idx >> 3, wd = idx & 7;
                dst[co * 8 + wd] = src[co * 256 + wd];  // 512 halves/co = 256 words
            }
        }
        __syncthreads();

        for (int ti = 0; ti < ntap; ti++) {
            int dy = c_tdy[par][ti], dx = c_tdx[par][ti];
            uint32_t A[2][4];
#pragma unroll
            for (int mi = 0; mi < 2; mi++) {
                int r  = warp_m * 2 + mi;
                int yy = r + dy;
                const uint32_t* px0 =
                    (const uint32_t*)&xs[((yy * 17) + grp + dx) * XPAD + 2 * tig];
                const uint32_t* px1 =
                    (const uint32_t*)&xs[((yy * 17) + grp + 8 + dx) * XPAD + 2 * tig];
                A[mi][0] = px0[0];   // (row grp,    k 2tig..+1)
                A[mi][1] = px1[0];   // (row grp+8,  k 2tig..+1)
                A[mi][2] = px0[4];   // (row grp,    k 2tig+8..+9)
                A[mi][3] = px1[4];   // (row grp+8,  k 2tig+8..+9)
            }
#pragma unroll
            for (int ni = 0; ni < 8; ni++) {
                const uint32_t* pb =
                    (const uint32_t*)&ws[((ti * 256) + nb + ni * 8 + grp) * KC + 2 * tig];
                uint32_t b0 = pb[0];   // (k 2tig..+1,   n grp)
                uint32_t b1 = pb[4];   // (k 2tig+8..+9, n grp)
                mma16816(acc[0][ni], A[0], b0, b1);
                mma16816(acc[1][ni], A[1], b0, b1);
            }
        }
    }

    // ---- store to parity planes g_zp[b][co][par][68][72]
    // C frag: c0,c1 -> (scol grp,   co 2tig, 2tig+1); c2,c3 -> (scol grp+8, same)
#pragma unroll
    for (int mi = 0; mi < 2; mi++) {
        int p = p0 + warp_m * 2 + mi;
        int qa = q0 + grp, qb = qa + 8;
#pragma unroll
        for (int ni = 0; ni < 8; ni++) {
            int co = nb + ni * 8 + 2 * tig;
            float* pl0 = g_zp + ((size_t)(b * 256 + co) * 4 + par) * (68 * 72) + p * 72;
            float* pl1 = pl0 + (size_t)4 * (68 * 72);   // co+1
            pl0[qa] = acc[mi][ni][0];
            pl1[qa] = acc[mi][ni][1];
            pl0[qb] = acc[mi][ni][2];
            pl1[qb] = acc[mi][ni][3];
        }
    }
}

// ---------------------------- Stage 2: FIR + epilogue ----------------------
// grid: (16 tiles of 32x32, 256 co, 8 b), 256 threads, 4 px/thread
__global__ __launch_bounds__(256) void stage2(const float* __restrict__ bias,
                                              const float* __restrict__ noise,
                                              const float* __restrict__ nstr,
                                              float* __restrict__ out) {
    int bx  = blockIdx.x;
    int my0 = (bx >> 2) * 32, mx0 = (bx & 3) * 32;
    int co  = blockIdx.y, b = blockIdx.z;
    int tid = threadIdx.x;

    __shared__ float zs[35][36];
    const float* zb = g_zp + (size_t)(b * 256 + co) * 4 * (68 * 72);
    for (int idx = tid; idx < 35 * 35; idx += 256) {
        int r = idx / 35, c = idx % 35;
        int zy = my0 + r, zx = mx0 + c;          // full-res z coords, <= 130
        zs[r][c] = zb[((zy & 1) * 2 + (zx & 1)) * (68 * 72) +
                      (zy >> 1) * 72 + (zx >> 1)];
    }
    __syncthreads();

    float ns = *nstr;
    float bv = bias[co];
    const float c4[4] = {0.25f, 0.75f, 0.75f, 0.25f};  // [1,3,3,1]/4 per axis
    float* op = out + ((size_t)(b * 256 + co) * 128 + my0) * 128 + mx0;

#pragma unroll
    for (int k = 0; k < 4; k++) {
        int pid = k * 256 + tid;
        int py = pid >> 5, px = pid & 31;
        float s = 0.f;
#pragma unroll
        for (int ky = 0; ky < 4; ky++) {
            float t = 0.f;
#pragma unroll
            for (int kx = 0; kx < 4; kx++) t += c4[kx] * zs[py + ky][px + kx];
            s += c4[ky] * t;
        }
        s += noise[(my0 + py) * 128 + mx0 + px] * ns + bv;
        s = (s >= 0.f ? s : 0.2f * s) * 1.41421356237309515f;
        op[py * 128 + px] = s;
    }
}

// ---------------------------------------------------------------------------
extern "C" void kernel_launch(void* const* d_in, const int* in_sizes, int n_in,
                              void* d_out, int out_size) {
    (void)in_sizes; (void)n_in; (void)out_size;
    const float* x     = (const float*)d_in[0];   // [8,512,64,64]
    const float* w     = (const float*)d_in[1];   // [256,512,3,3]
    const float* bias  = (const float*)d_in[2];   // [256]
    const float* noise = (const float*)d_in[3];   // [128,128]
    const float* nstr  = (const float*)d_in[4];   // scalar
    float* out = (float*)d_out;                   // [8,256,128,128]

    prep_weights<<<256, 256>>>(w);

    dim3 g1(85, 4, 8);        // 17x5 spatial tiles, 4 parities, 8 batches
    stage1<<<g1, 256>>>(x);

    dim3 g2(16, 256, 8);
    stage2<<<g2, 256>>>(bias, noise, nstr, out);
}

// round 7
// speedup vs baseline: 3.2483x; 1.3413x over previous
#include <cuda_runtime.h>
#include <cuda_fp16.h>
#include <stdint.h>
#include <math.h>

// ---------------------------------------------------------------------------
// StyleGAN2 up-2x synthesis layer:
//   prep_w: per-cout L2-normalize + flip -> g_whh[tap][co][cin] (fp16)
//   prep_x: x fp32 -> zero-padded fp16 g_xh[b][c][68][72], g_xh[y][x']=x[y-1][x'-1]
//   stage1: 4 parity-plane GEMMs via mma.sync m16n8k16 (fp16 in, fp32 acc),
//           CTA = 256 spatial x 128 co, register-double-buffered fills,
//           z parity planes stored fp16 [b][co][par][68][72]
//   stage2: recompose + 4x4 separable FIR + noise + bias + lrelu*sqrt2
// ---------------------------------------------------------------------------

__device__ __half g_whh[9 * 256 * 512];                          // [tap][co][cin]
__device__ __half g_xh[(size_t)8 * 512 * 68 * 72];               // [b][c][68][72]
__device__ __half g_zph[(size_t)8 * 256 * 4 * 68 * 72];          // [b][co][par][68][72]

__constant__ int c_ntap[4]     = {1, 2, 2, 4};
__constant__ int c_tapid[4][4] = {{4,0,0,0},{3,5,0,0},{1,7,0,0},{0,2,6,8}};
__constant__ int c_tdy[4][4]   = {{0,0,0,0},{0,0,0,0},{0,1,0,0},{0,0,1,1}};
__constant__ int c_tdx[4][4]   = {{0,0,0,0},{0,1,0,0},{0,0,0,0},{0,1,0,1}};

// ---------------------------- prep_weights ---------------------------------
__global__ void prep_weights(const float* __restrict__ w) {
    int co  = blockIdx.x;
    int tid = threadIdx.x;
    const float* wc = w + (size_t)co * 4608;   // [512][3][3]

    float s = 0.f;
    for (int i = tid; i < 4608; i += 256) { float v = wc[i]; s += v * v; }
    __shared__ float red[256];
    red[tid] = s;
    __syncthreads();
    for (int off = 128; off > 0; off >>= 1) {
        if (tid < off) red[tid] += red[tid + off];
        __syncthreads();
    }
    float inv = rsqrtf(red[0] + 1e-8f);

    for (int i = tid; i < 4608; i += 256) {
        int cin = i / 9, r = i % 9;
        int ty = r / 3, tx = r % 3;
        float v = wc[cin * 9 + (2 - ty) * 3 + (2 - tx)] * inv;
        g_whh[((size_t)r * 256 + co) * 512 + cin] = __float2half_rn(v);
    }
}

// ---------------------------- prep_x ---------------------------------------
// g_xh[b][c][y][x'] = x[b][c][y-1][x'-1] for y,x' in [1,65); zero elsewhere.
__global__ void prep_x(const float* __restrict__ x) {
    int bc  = blockIdx.x;              // 4096 = 8*512
    int tid = threadIdx.x;
    const float* src = x + (size_t)bc * 4096;
    __half* dst = g_xh + (size_t)bc * (68 * 72);

    for (int u = tid; u < 68 * 36; u += 256) {   // 2448 half2 per (b,c)
        int y = u / 36, xp = u % 36;
        int c0 = 2 * xp, c1 = 2 * xp + 1;
        float v0 = 0.f, v1 = 0.f;
        if (y >= 1 && y <= 64) {
            if (c0 >= 1 && c0 <= 64) v0 = src[(y - 1) * 64 + c0 - 1];
            if (c1 >= 1 && c1 <= 64) v1 = src[(y - 1) * 64 + c1 - 1];
        }
        *(__half2*)&dst[y * 72 + c0] =
            __halves2half2(__float2half_rn(v0), __float2half_rn(v1));
    }
}

// ---------------------------- stage1: parity GEMMs -------------------------
// grid (25 tiles, par*2+cohalf, b), 256 threads.
// CTA: M = 128 co (A = weights), N = 256 spatial (16 p-rows x 16 q).
// Warp: co 64 (warp_m, 4 mi of m16) x spatial 64 (warp_n -> 4 p-rows; qo 0..1).
#define KC 16
#define NXU (17 * 9 * 16)      // 2448 uints per x chunk (17 yy, 9 xpairs, 16 c)

__device__ __forceinline__ void mma16816(float* d, uint32_t a0, uint32_t a1,
                                         uint32_t a2, uint32_t a3,
                                         uint32_t b0, uint32_t b1) {
    asm volatile(
        "mma.sync.aligned.m16n8k16.row.col.f32.f16.f16.f32 "
        "{%0,%1,%2,%3}, {%4,%5,%6,%7}, {%8,%9}, {%0,%1,%2,%3};\n"
        : "+f"(d[0]), "+f"(d[1]), "+f"(d[2]), "+f"(d[3])
        : "r"(a0), "r"(a1), "r"(a2), "r"(a3), "r"(b0), "r"(b1));
}

__global__ __launch_bounds__(256, 1) void stage1() {
    __shared__ __align__(16) __half xs[17 * 18 * 24];   // [yy][xx<18][c pad 24]
    __shared__ __align__(16) __half ws[4 * 128 * 24];   // [ti][co<128][c pad 24]

    int tile = blockIdx.x;                  // 0..24
    int tr = tile / 5, tc = tile % 5;
    int p0 = (tr == 4) ? 50 : tr * 16;      // {0,16,32,48,50} covers [0,66)
    int q0 = (tc == 4) ? 50 : tc * 16;
    int par = blockIdx.y >> 1;
    int co0 = (blockIdx.y & 1) * 128;
    int b   = blockIdx.z;
    int ntap = c_ntap[par];
    int nwu  = ntap * 1024;                 // weight uints per chunk

    int tid = threadIdx.x, lane = tid & 31, wid = tid >> 5;
    int warp_m = wid & 1;                   // co half of CTA tile
    int warp_n = wid >> 1;                  // p-row group (0..3)
    int tig = lane & 3, grp = lane >> 2;

    float acc[4][4][2][4];                  // [mi][pl][qo][frag]
#pragma unroll
    for (int a = 0; a < 4; a++)
#pragma unroll
        for (int p = 0; p < 4; p++)
#pragma unroll
            for (int q = 0; q < 2; q++)
#pragma unroll
                for (int k = 0; k < 4; k++) acc[a][p][q][k] = 0.f;

    const uint32_t* xsrc = (const uint32_t*)(g_xh + (size_t)b * 512 * (68 * 72));
    uint32_t xbuf[10], wbuf[16];

    // ---- prefetch chunk 0
#pragma unroll
    for (int i = 0; i < 10; i++) {
        int u = i * 256 + tid;
        if (u < NXU) {
            int yy = u / 144, rem = u % 144;
            int xp = rem >> 4, c = rem & 15;
            xbuf[i] = xsrc[(((size_t)c * 68) + p0 + yy) * 36 + (q0 >> 1) + xp];
        }
    }
#pragma unroll
    for (int i = 0; i < 16; i++) {
        int u = i * 256 + tid;
        if (u < nwu) {
            int ti = u >> 10, co = (u >> 3) & 127, cp = u & 7;
            wbuf[i] = *(const uint32_t*)
                &g_whh[((size_t)c_tapid[par][ti] * 256 + co0 + co) * 512 + 2 * cp];
        }
    }

    for (int c0 = 0; c0 < 512; c0 += KC) {
        __syncthreads();
        // ---- STS buffered chunk
#pragma unroll
        for (int i = 0; i < 10; i++) {
            int u = i * 256 + tid;
            if (u < NXU) {
                int yy = u / 144, rem = u % 144;
                int xp = rem >> 4, c = rem & 15;
                __half2 h2 = *(__half2*)&xbuf[i];
                xs[(yy * 18 + 2 * xp) * 24 + c] = h2.x;
                if (2 * xp + 1 < 18) xs[(yy * 18 + 2 * xp + 1) * 24 + c] = h2.y;
            }
        }
#pragma unroll
        for (int i = 0; i < 16; i++) {
            int u = i * 256 + tid;
            if (u < nwu) {
                int ti = u >> 10, co = (u >> 3) & 127, cp = u & 7;
                *(uint32_t*)&ws[(ti * 128 + co) * 24 + 2 * cp] = wbuf[i];
            }
        }
        __syncthreads();

        // ---- prefetch next chunk (overlaps compute below)
        int cn = c0 + KC;
        if (cn < 512) {
#pragma unroll
            for (int i = 0; i < 10; i++) {
                int u = i * 256 + tid;
                if (u < NXU) {
                    int yy = u / 144, rem = u % 144;
                    int xp = rem >> 4, c = rem & 15;
                    xbuf[i] = xsrc[(((size_t)(cn + c) * 68) + p0 + yy) * 36 +
                                   (q0 >> 1) + xp];
                }
            }
#pragma unroll
            for (int i = 0; i < 16; i++) {
                int u = i * 256 + tid;
                if (u < nwu) {
                    int ti = u >> 10, co = (u >> 3) & 127, cp = u & 7;
                    wbuf[i] = *(const uint32_t*)
                        &g_whh[((size_t)c_tapid[par][ti] * 256 + co0 + co) * 512 +
                               cn + 2 * cp];
                }
            }
        }

        // ---- compute
        for (int ti = 0; ti < ntap; ti++) {
            int dy = c_tdy[par][ti], dx = c_tdx[par][ti];
            uint32_t breg[4][2][2];
#pragma unroll
            for (int pl = 0; pl < 4; pl++)
#pragma unroll
                for (int qo = 0; qo < 2; qo++) {
                    int yy = warp_n * 4 + pl + dy;
                    int xx = qo * 8 + grp + dx;
                    const uint32_t* pB =
                        (const uint32_t*)&xs[(yy * 18 + xx) * 24 + 2 * tig];
                    breg[pl][qo][0] = pB[0];
                    breg[pl][qo][1] = pB[4];
                }
#pragma unroll
            for (int mi = 0; mi < 4; mi++) {
                const uint32_t* pA = (const uint32_t*)
                    &ws[(ti * 128 + warp_m * 64 + mi * 16 + grp) * 24 + 2 * tig];
                uint32_t a0 = pA[0], a2 = pA[4];
                uint32_t a1 = pA[96], a3 = pA[100];    // +8 co rows = +96 words
#pragma unroll
                for (int pl = 0; pl < 4; pl++)
#pragma unroll
                    for (int qo = 0; qo < 2; qo++)
                        mma16816(acc[mi][pl][qo], a0, a1, a2, a3,
                                 breg[pl][qo][0], breg[pl][qo][1]);
            }
        }
    }

    // ---- epilogue: fp16 stores to parity planes
    __half* zb = g_zph + (((size_t)b * 256 + co0) * 4 + par) * (68 * 72);
    const size_t co_str = (size_t)4 * 68 * 72;
#pragma unroll
    for (int mi = 0; mi < 4; mi++) {
        int co = warp_m * 64 + mi * 16 + grp;
#pragma unroll
        for (int pl = 0; pl < 4; pl++) {
            int p = p0 + warp_n * 4 + pl;
#pragma unroll
            for (int qo = 0; qo < 2; qo++) {
                int q = q0 + qo * 8 + 2 * tig;
                __half* base = zb + (size_t)co * co_str + p * 72 + q;
                float* f = acc[mi][pl][qo];
                *(__half2*)base =
                    __halves2half2(__float2half_rn(f[0]), __float2half_rn(f[1]));
                *(__half2*)(base + 8 * co_str) =
                    __halves2half2(__float2half_rn(f[2]), __float2half_rn(f[3]));
            }
        }
    }
}

// ---------------------------- stage2: FIR + epilogue -----------------------
__global__ __launch_bounds__(256) void stage2(const float* __restrict__ bias,
                                              const float* __restrict__ noise,
                                              const float* __restrict__ nstr,
                                              float* __restrict__ out) {
    int bx  = blockIdx.x;
    int my0 = (bx >> 2) * 32, mx0 = (bx & 3) * 32;
    int co  = blockIdx.y, b = blockIdx.z;
    int tid = threadIdx.x;

    __shared__ float zs[35][36];
    const __half* zb = g_zph + (size_t)(b * 256 + co) * 4 * (68 * 72);
    for (int idx = tid; idx < 35 * 35; idx += 256) {
        int r = idx / 35, c = idx % 35;
        int zy = my0 + r, zx = mx0 + c;          // full-res z coords, <= 130
        zs[r][c] = __half2float(zb[((zy & 1) * 2 + (zx & 1)) * (68 * 72) +
                                   (zy >> 1) * 72 + (zx >> 1)]);
    }
    __syncthreads();

    float ns = *nstr;
    float bv = bias[co];
    const float c4[4] = {0.25f, 0.75f, 0.75f, 0.25f};
    float* op = out + ((size_t)(b * 256 + co) * 128 + my0) * 128 + mx0;

#pragma unroll
    for (int k = 0; k < 4; k++) {
        int pid = k * 256 + tid;
        int py = pid >> 5, px = pid & 31;
        float s = 0.f;
#pragma unroll
        for (int ky = 0; ky < 4; ky++) {
            float t = 0.f;
#pragma unroll
            for (int kx = 0; kx < 4; kx++) t += c4[kx] * zs[py + ky][px + kx];
            s += c4[ky] * t;
        }
        s += noise[(my0 + py) * 128 + mx0 + px] * ns + bv;
        s = (s >= 0.f ? s : 0.2f * s) * 1.41421356237309515f;
        op[py * 128 + px] = s;
    }
}

// ---------------------------------------------------------------------------
extern "C" void kernel_launch(void* const* d_in, const int* in_sizes, int n_in,
                              void* d_out, int out_size) {
    (void)in_sizes; (void)n_in; (void)out_size;
    const float* x     = (const float*)d_in[0];   // [8,512,64,64]
    const float* w     = (const float*)d_in[1];   // [256,512,3,3]
    const float* bias  = (const float*)d_in[2];   // [256]
    const float* noise = (const float*)d_in[3];   // [128,128]
    const float* nstr  = (const float*)d_in[4];   // scalar
    float* out = (float*)d_out;                   // [8,256,128,128]

    prep_weights<<<256, 256>>>(w);
    prep_x<<<4096, 256>>>(x);

    dim3 g1(25, 8, 8);        // 5x5 spatial tiles, par*2+cohalf, batches
    stage1<<<g1, 256>>>();

    dim3 g2(16, 256, 8);
    stage2<<<g2, 256>>>(bias, noise, nstr, out);
}

// round 9
// speedup vs baseline: 4.8525x; 1.4938x over previous
#include <cuda_runtime.h>
#include <cuda_fp16.h>
#include <stdint.h>
#include <math.h>

// ---------------------------------------------------------------------------
// StyleGAN2 up-2x synthesis layer (mma.sync path; tcgen05 unavailable on this
// ptxas target):
//   prep_w : L2-normalize + flip -> g_whh[tap][co][cin] fp16
//   prep_x : NCHW fp32 -> NHWC fp16 halo buffer g_xh2[b][74][68][512]
//            g_xh2[y][x'] = x[y-1][x'-1] (zero outside)
//   stage1 : 4 parity-plane GEMMs, CTA = 128co x 128spatial, warp 64co x 32sp,
//            cp.async 2-stage smem pipeline, occupancy 2.
//            z fp16 [b][co][par][68][72]
//   stage2 : recompose + 4x4 separable FIR + noise + bias + lrelu*sqrt2
// ---------------------------------------------------------------------------

__device__ __half g_whh[9 * 256 * 512];                    // [tap][co][cin]
__device__ __half g_xh2[(size_t)8 * 74 * 68 * 512];        // [b][y][x'][cin]
__device__ __half g_zph[(size_t)8 * 256 * 4 * 68 * 72];    // [b][co][par][68][72]

__constant__ int c_ntap[4]     = {1, 2, 2, 4};
__constant__ int c_tapid[4][4] = {{4,0,0,0},{3,5,0,0},{1,7,0,0},{0,2,6,8}};
__constant__ int c_tdy[4][4]   = {{0,0,0,0},{0,0,0,0},{0,1,0,0},{0,0,1,1}};
__constant__ int c_tdx[4][4]   = {{0,0,0,0},{0,1,0,0},{0,0,0,0},{0,1,0,1}};

#define CP16(d, s) asm volatile("cp.async.cg.shared.global [%0], [%1], 16;" :: "r"(d), "l"(s))
#define CP_COMMIT() asm volatile("cp.async.commit_group;" ::: "memory")
#define CP_WAIT1()  asm volatile("cp.async.wait_group 1;" ::: "memory")
#define CP_WAIT0()  asm volatile("cp.async.wait_group 0;" ::: "memory")

static __device__ __forceinline__ uint32_t smem_u32(const void* p) {
    uint32_t a;
    asm("{ .reg .u64 t; cvta.to.shared.u64 t, %1; cvt.u32.u64 %0, t; }"
        : "=r"(a) : "l"(p));
    return a;
}

__device__ __forceinline__ void mma16816(float* d, uint32_t a0, uint32_t a1,
                                         uint32_t a2, uint32_t a3,
                                         uint32_t b0, uint32_t b1) {
    asm volatile(
        "mma.sync.aligned.m16n8k16.row.col.f32.f16.f16.f32 "
        "{%0,%1,%2,%3}, {%4,%5,%6,%7}, {%8,%9}, {%0,%1,%2,%3};\n"
        : "+f"(d[0]), "+f"(d[1]), "+f"(d[2]), "+f"(d[3])
        : "r"(a0), "r"(a1), "r"(a2), "r"(a3), "r"(b0), "r"(b1));
}

// ---------------------------- prep_weights ---------------------------------
__global__ void prep_weights(const float* __restrict__ w) {
    int co = blockIdx.x, tid = threadIdx.x;
    const float* wc = w + (size_t)co * 4608;
    float s = 0.f;
    for (int i = tid; i < 4608; i += 256) { float v = wc[i]; s += v * v; }
    __shared__ float red[256];
    red[tid] = s; __syncthreads();
    for (int off = 128; off > 0; off >>= 1) {
        if (tid < off) red[tid] += red[tid + off];
        __syncthreads();
    }
    float inv = rsqrtf(red[0] + 1e-8f);
    for (int i = tid; i < 4608; i += 256) {
        int cin = i / 9, r = i % 9, ty = r / 3, tx = r % 3;
        float v = wc[cin * 9 + (2 - ty) * 3 + (2 - tx)] * inv;
        g_whh[((size_t)r * 256 + co) * 512 + cin] = __float2half_rn(v);
    }
}

// ---------------------------- prep_x (NCHW->NHWC halo) ---------------------
__global__ void prep_x(const float* __restrict__ x) {
    int gy = blockIdx.x, b = blockIdx.y, tid = threadIdx.x;   // gy in [0,74)
    __half2* dst = (__half2*)(g_xh2 + ((size_t)(b * 74 + gy)) * 68 * 512);
    if (gy == 0 || gy >= 65) {
        __half2 z = __halves2half2(__float2half_rn(0.f), __float2half_rn(0.f));
        for (int u = tid; u < 68 * 256; u += 256) dst[u] = z;
        return;
    }
    __shared__ __half sm[256 * 66];
    const float* src = x + (size_t)b * 512 * 4096 + (gy - 1) * 64;
    for (int h = 0; h < 2; h++) {
        for (int u = tid; u < 256 * 64; u += 256) {
            int cl = u >> 6, xx = u & 63;
            sm[cl * 66 + xx] =
                __float2half_rn(src[(size_t)(256 * h + cl) * 4096 + xx]);
        }
        __syncthreads();
        for (int u = tid; u < 68 * 128; u += 256) {
            int xp = u >> 7, cpl = u & 127;
            int cp = 128 * h + cpl;
            __half2 v;
            if (xp >= 1 && xp < 65)
                v = __halves2half2(sm[(2 * cpl) * 66 + xp - 1],
                                   sm[(2 * cpl + 1) * 66 + xp - 1]);
            else
                v = __halves2half2(__float2half_rn(0.f), __float2half_rn(0.f));
            dst[xp * 256 + cp] = v;
        }
        __syncthreads();
    }
}

// ---------------------------- stage1: parity GEMMs -------------------------
// grid (45 = 9 row-tiles x 5 col-tiles, par*2+cohalf, b), 256 threads, occ 2.
// CTA: 128 co x 128 spatial (8 p-rows x 16 q-cols). Warp: 64 co x 32 spatial.
// K pipeline: KC=16 cin/chunk, 32 chunks, cp.async double-buffered smem.
#define KC 16
#define XS_H (153 * 24)                 // 9*17 cells, stride 24 halves
#define WS_H (4 * 128 * 24)             // [ti][co<128][c pad 24]
#define STG_H (XS_H + WS_H)             // halves per stage (3672+12288=15960)
#define S1_SMEM (2 * STG_H * 2)         // bytes (63840)

__global__ __launch_bounds__(256, 2) void stage1() {
    extern __shared__ __align__(16) __half sm1[];

    int tile = blockIdx.x;
    int tr = tile / 5, tc = tile % 5;
    int p0 = tr * 8;                          // rows 0..71 (p<66 kept at store)
    int q0 = (tc == 4) ? 50 : tc * 16;        // {0,16,32,48,50} covers [0,66)
    int par = blockIdx.y >> 1;
    int co0 = (blockIdx.y & 1) * 128;
    int b   = blockIdx.z;
    int ntap = c_ntap[par];
    int ncp  = 306 + ntap * 256;              // cp16 ops per chunk

    int tid = threadIdx.x, lane = tid & 31, wid = tid >> 5;
    int warp_m = wid & 1;                     // co half (0..1) -> 64 co
    int warp_n = wid >> 1;                    // spatial 32-group (0..3)
    int tig = lane & 3, grp = lane >> 2;

    const __half* xh = g_xh2 + (size_t)b * 74 * 68 * 512;

    float acc[4][4][4];                       // [mi][ni][frag]
#pragma unroll
    for (int i = 0; i < 4; i++)
#pragma unroll
        for (int j = 0; j < 4; j++)
#pragma unroll
            for (int k = 0; k < 4; k++) acc[i][j][k] = 0.f;

    uint32_t sbase = smem_u32(sm1);

    // ---- fill helper (macro to keep regs low)
#define FILL_CHUNK(CI, S)                                                      \
    do {                                                                       \
        int _c0 = (CI) * KC;                                                   \
        uint32_t _xs = sbase + (S) * (STG_H * 2);                              \
        uint32_t _ws = _xs + XS_H * 2;                                         \
        for (int u = tid; u < ncp; u += 256) {                                 \
            const __half* src;                                                 \
            uint32_t dst;                                                      \
            if (u < 306) {                                                     \
                int cell = u >> 1, seg = u & 1;                                \
                int yy = cell / 17, xx = cell % 17;                            \
                src = xh + ((size_t)((p0 + yy) * 68 + q0 + xx)) * 512 + _c0 +  \
                      seg * 8;                                                 \
                dst = _xs + (cell * 24 + seg * 8) * 2;                         \
            } else {                                                           \
                int v = u - 306;                                               \
                int ti = v >> 8, r = v & 255, co = r >> 1, seg = r & 1;        \
                src = g_whh + ((size_t)c_tapid[par][ti] * 256 + co0 + co) *    \
                          512 + _c0 + seg * 8;                                 \
                dst = _ws + ((ti * 128 + co) * 24 + seg * 8) * 2;              \
            }                                                                  \
            CP16(dst, src);                                                    \
        }                                                                      \
        CP_COMMIT();                                                           \
    } while (0)

    FILL_CHUNK(0, 0);

    for (int ci = 0; ci < 32; ci++) {
        if (ci + 1 < 32) { FILL_CHUNK(ci + 1, (ci + 1) & 1); CP_WAIT1(); }
        else             { CP_WAIT0(); }
        __syncthreads();

        const __half* xs = sm1 + (ci & 1) * STG_H;
        const __half* ws = xs + XS_H;

        for (int ti = 0; ti < ntap; ti++) {
            int dy = c_tdy[par][ti], dx = c_tdx[par][ti];
            uint32_t breg[4][2];
#pragma unroll
            for (int ni = 0; ni < 4; ni++) {
                int cell = warp_n * 32 + ni * 8 + grp;
                int yy = (cell >> 4) + dy, xx = (cell & 15) + dx;
                const uint32_t* pB =
                    (const uint32_t*)&xs[(yy * 17 + xx) * 24 + 2 * tig];
                breg[ni][0] = pB[0];
                breg[ni][1] = pB[4];
            }
#pragma unroll
            for (int mi = 0; mi < 4; mi++) {
                const uint32_t* pA = (const uint32_t*)
                    &ws[(ti * 128 + warp_m * 64 + mi * 16 + grp) * 24 + 2 * tig];
                uint32_t a0 = pA[0], a2 = pA[4];
                uint32_t a1 = pA[96], a3 = pA[100];   // +8 co rows = +96 words
#pragma unroll
                for (int ni = 0; ni < 4; ni++)
                    mma16816(acc[mi][ni], a0, a1, a2, a3,
                             breg[ni][0], breg[ni][1]);
            }
        }
        __syncthreads();
    }

    // ---- store z fp16 [b][co][par][68][72]
    const size_t pstr = 68 * 72;
#pragma unroll
    for (int mi = 0; mi < 4; mi++) {
        int coA = co0 + warp_m * 64 + mi * 16 + grp;
#pragma unroll
        for (int ni = 0; ni < 4; ni++) {
            int n = warp_n * 32 + ni * 8 + 2 * tig;
            int p = p0 + (n >> 4), q = q0 + (n & 15);
            if (p < 66) {
                float* f = acc[mi][ni];
                __half* z0 = g_zph +
                    (((size_t)(b * 256 + coA) * 4) + par) * pstr + p * 72 + q;
                *(__half2*)z0 =
                    __halves2half2(__float2half_rn(f[0]), __float2half_rn(f[1]));
                *(__half2*)(z0 + 8 * 4 * pstr) =
                    __halves2half2(__float2half_rn(f[2]), __float2half_rn(f[3]));
            }
        }
    }
#undef FILL_CHUNK
}

// ---------------------------- stage2: FIR + epilogue -----------------------
__global__ __launch_bounds__(256) void stage2(const float* __restrict__ bias,
                                              const float* __restrict__ noise,
                                              const float* __restrict__ nstr,
                                              float* __restrict__ out) {
    int bx  = blockIdx.x;
    int my0 = (bx >> 2) * 32, mx0 = (bx & 3) * 32;
    int co  = blockIdx.y, b = blockIdx.z;
    int tid = threadIdx.x;

    __shared__ float zs[35][36];
    const __half* zb = g_zph + (size_t)(b * 256 + co) * 4 * (68 * 72);
    for (int idx = tid; idx < 35 * 35; idx += 256) {
        int r = idx / 35, c = idx % 35;
        int zy = my0 + r, zx = mx0 + c;
        zs[r][c] = __half2float(zb[((zy & 1) * 2 + (zx & 1)) * (68 * 72) +
                                   (zy >> 1) * 72 + (zx >> 1)]);
    }
    __syncthreads();

    float ns = *nstr;
    float bv = bias[co];
    const float c4[4] = {0.25f, 0.75f, 0.75f, 0.25f};
    float* op = out + ((size_t)(b * 256 + co) * 128 + my0) * 128 + mx0;

#pragma unroll
    for (int k = 0; k < 4; k++) {
        int pid = k * 256 + tid;
        int py = pid >> 5, px = pid & 31;
        float s = 0.f;
#pragma unroll
        for (int ky = 0; ky < 4; ky++) {
            float t = 0.f;
#pragma unroll
            for (int kx = 0; kx < 4; kx++) t += c4[kx] * zs[py + ky][px + kx];
            s += c4[ky] * t;
        }
        s += noise[(my0 + py) * 128 + mx0 + px] * ns + bv;
        s = (s >= 0.f ? s : 0.2f * s) * 1.41421356237309515f;
        op[py * 128 + px] = s;
    }
}

// ---------------------------------------------------------------------------
extern "C" void kernel_launch(void* const* d_in, const int* in_sizes, int n_in,
                              void* d_out, int out_size) {
    (void)in_sizes; (void)n_in; (void)out_size;
    const float* x     = (const float*)d_in[0];   // [8,512,64,64]
    const float* w     = (const float*)d_in[1];   // [256,512,3,3]
    const float* bias  = (const float*)d_in[2];   // [256]
    const float* noise = (const float*)d_in[3];   // [128,128]
    const float* nstr  = (const float*)d_in[4];   // scalar
    float* out = (float*)d_out;                   // [8,256,128,128]

    cudaFuncSetAttribute(stage1, cudaFuncAttributeMaxDynamicSharedMemorySize,
                         S1_SMEM);

    prep_weights<<<256, 256>>>(w);
    dim3 gx(74, 8);
    prep_x<<<gx, 256>>>(x);

    dim3 g1(45, 8, 8);          // 9x5 tiles, par*2+cohalf, batches
    stage1<<<g1, 256, S1_SMEM>>>();

    dim3 g2(16, 256, 8);
    stage2<<<g2, 256>>>(bias, noise, nstr, out);
}

// round 11
// speedup vs baseline: 4.9378x; 1.0176x over previous
#include <cuda_runtime.h>
#include <cuda_fp16.h>
#include <stdint.h>
#include <math.h>

// ---------------------------------------------------------------------------
// StyleGAN2 up-2x synthesis layer (mma.sync; tcgen05 not available on this
// ptxas target):
//   prep_w : L2-normalize + flip -> g_whh[tap][co][cin] fp16
//   prep_x : NCHW fp32 -> NHWC fp16 halo buffer g_xh2[b][74][68][512]
//   stage1 : 4 parity GEMMs, N = flattened spatial n=p*66+q (35 tiles of 128,
//            ~3% pad vs 32%), CTA = 128co x 128n, cp.async double buffer.
//            z fp16 pair-interleaved [b][par][n>>1][co][2]
//   stage2 : separable 4x4 FIR (h-pass + v-pass, fp32 smem) + noise + bias
//            + lrelu*sqrt2
// ---------------------------------------------------------------------------

__device__ __half g_whh[9 * 256 * 512];                    // [tap][co][cin]
__device__ __half g_xh2[(size_t)8 * 74 * 68 * 512];        // [b][y][x'][cin]
__device__ __half g_z[(size_t)8 * 4 * 2240 * 512];         // [b][par][n/2][co][2]

__constant__ int c_ntap[4]     = {1, 2, 2, 4};
__constant__ int c_tapid[4][4] = {{4,0,0,0},{3,5,0,0},{1,7,0,0},{0,2,6,8}};
__constant__ int c_tdy[4][4]   = {{0,0,0,0},{0,0,0,0},{0,1,0,0},{0,0,1,1}};
__constant__ int c_tdx[4][4]   = {{0,0,0,0},{0,1,0,0},{0,0,0,0},{0,1,0,1}};

#define CP16(d, s) asm volatile("cp.async.cg.shared.global [%0], [%1], 16;" :: "r"(d), "l"(s))
#define CP_COMMIT() asm volatile("cp.async.commit_group;" ::: "memory")
#define CP_WAIT1()  asm volatile("cp.async.wait_group 1;" ::: "memory")
#define CP_WAIT0()  asm volatile("cp.async.wait_group 0;" ::: "memory")

static __device__ __forceinline__ uint32_t smem_u32(const void* p) {
    uint32_t a;
    asm("{ .reg .u64 t; cvta.to.shared.u64 t, %1; cvt.u32.u64 %0, t; }"
        : "=r"(a) : "l"(p));
    return a;
}

__device__ __forceinline__ void mma16816(float* d, uint32_t a0, uint32_t a1,
                                         uint32_t a2, uint32_t a3,
                                         uint32_t b0, uint32_t b1) {
    asm volatile(
        "mma.sync.aligned.m16n8k16.row.col.f32.f16.f16.f32 "
        "{%0,%1,%2,%3}, {%4,%5,%6,%7}, {%8,%9}, {%0,%1,%2,%3};\n"
        : "+f"(d[0]), "+f"(d[1]), "+f"(d[2]), "+f"(d[3])
        : "r"(a0), "r"(a1), "r"(a2), "r"(a3), "r"(b0), "r"(b1));
}

// ---------------------------- prep_weights ---------------------------------
__global__ void prep_weights(const float* __restrict__ w) {
    int co = blockIdx.x, tid = threadIdx.x;
    const float* wc = w + (size_t)co * 4608;
    float s = 0.f;
    for (int i = tid; i < 4608; i += 256) { float v = wc[i]; s += v * v; }
    __shared__ float red[256];
    red[tid] = s; __syncthreads();
    for (int off = 128; off > 0; off >>= 1) {
        if (tid < off) red[tid] += red[tid + off];
        __syncthreads();
    }
    float inv = rsqrtf(red[0] + 1e-8f);
    for (int i = tid; i < 4608; i += 256) {
        int cin = i / 9, r = i % 9, ty = r / 3, tx = r % 3;
        float v = wc[cin * 9 + (2 - ty) * 3 + (2 - tx)] * inv;
        g_whh[((size_t)r * 256 + co) * 512 + cin] = __float2half_rn(v);
    }
}

// ---------------------------- prep_x (NCHW->NHWC halo) ---------------------
__global__ void prep_x(const float* __restrict__ x) {
    int gy = blockIdx.x, b = blockIdx.y, tid = threadIdx.x;   // gy in [0,74)
    __half2* dst = (__half2*)(g_xh2 + ((size_t)(b * 74 + gy)) * 68 * 512);
    if (gy == 0 || gy >= 65) {
        __half2 z = __halves2half2(__float2half_rn(0.f), __float2half_rn(0.f));
        for (int u = tid; u < 68 * 256; u += 256) dst[u] = z;
        return;
    }
    __shared__ __half sm[256 * 66];
    const float* src = x + (size_t)b * 512 * 4096 + (gy - 1) * 64;
    for (int h = 0; h < 2; h++) {
        for (int u = tid; u < 256 * 64; u += 256) {
            int cl = u >> 6, xx = u & 63;
            sm[cl * 66 + xx] =
                __float2half_rn(src[(size_t)(256 * h + cl) * 4096 + xx]);
        }
        __syncthreads();
        for (int u = tid; u < 68 * 128; u += 256) {
            int xp = u >> 7, cpl = u & 127;
            int cp = 128 * h + cpl;
            __half2 v;
            if (xp >= 1 && xp < 65)
                v = __halves2half2(sm[(2 * cpl) * 66 + xp - 1],
                                   sm[(2 * cpl + 1) * 66 + xp - 1]);
            else
                v = __halves2half2(__float2half_rn(0.f), __float2half_rn(0.f));
            dst[xp * 256 + cp] = v;
        }
        __syncthreads();
    }
}

// ---------------------------- stage1: parity GEMMs -------------------------
// grid (35 n-tiles, par*2+cohalf, b), 256 threads, occ 2.
// CTA: 128 co x 128 flattened-n. Warp: 64 co x 32 n. KC=16 cin/chunk.
#define KC 16
#define XS_H (272 * 24)                 // 4 rows x 68 cols cells, stride 24
#define WS_H (4 * 128 * 24)
#define STG_H (XS_H + WS_H)             // 18816 halves
#define S1_SMEM (2 * STG_H * 2)         // 75264 B

__global__ __launch_bounds__(256, 2) void stage1() {
    extern __shared__ __align__(16) __half sm1[];

    int n0 = blockIdx.x * 128;
    int p_lo = n0 / 66;
    int par = blockIdx.y >> 1;
    int co0 = (blockIdx.y & 1) * 128;
    int b   = blockIdx.z;
    int ntap = c_ntap[par];
    int ncp  = 544 + ntap * 256;

    int tid = threadIdx.x, lane = tid & 31, wid = tid >> 5;
    int warp_m = wid & 1;                     // co half -> 64 co
    int warp_n = wid >> 1;                    // n 32-group
    int tig = lane & 3, grp = lane >> 2;

    const __half* xh = g_xh2 + (size_t)b * 74 * 68 * 512;

    // B-fragment cell bases (flattened n -> (row,col) in 4x68 window)
    int bcell[4];
#pragma unroll
    for (int ni = 0; ni < 4; ni++) {
        int n = n0 + warp_n * 32 + ni * 8 + grp;
        int p = n / 66, q = n - p * 66;
        bcell[ni] = (p - p_lo) * 68 + q;
    }

    float acc[4][4][4];
#pragma unroll
    for (int i = 0; i < 4; i++)
#pragma unroll
        for (int j = 0; j < 4; j++)
#pragma unroll
            for (int k = 0; k < 4; k++) acc[i][j][k] = 0.f;

    uint32_t sbase = smem_u32(sm1);

#define FILL_CHUNK(CI, S)                                                      \
    do {                                                                       \
        int _c0 = (CI) * KC;                                                   \
        uint32_t _xs = sbase + (S) * (STG_H * 2);                              \
        uint32_t _ws = _xs + XS_H * 2;                                         \
        for (int u = tid; u < ncp; u += 256) {                                 \
            const __half* src;                                                 \
            uint32_t dst;                                                      \
            if (u < 544) {                                                     \
                int r = u / 136, rem2 = u % 136;                               \
                int colx = rem2 >> 1, seg = rem2 & 1;                          \
                src = xh + ((size_t)((p_lo + r) * 68 + colx)) * 512 + _c0 +    \
                      seg * 8;                                                 \
                dst = _xs + ((r * 68 + colx) * 24 + seg * 8) * 2;              \
            } else {                                                           \
                int v = u - 544;                                               \
                int ti = v >> 8, r8 = v & 255, co = r8 >> 1, seg = r8 & 1;     \
                src = g_whh + ((size_t)c_tapid[par][ti] * 256 + co0 + co) *    \
                          512 + _c0 + seg * 8;                                 \
                dst = _ws + ((ti * 128 + co) * 24 + seg * 8) * 2;              \
            }                                                                  \
            CP16(dst, src);                                                    \
        }                                                                      \
        CP_COMMIT();                                                           \
    } while (0)

    FILL_CHUNK(0, 0);

    for (int ci = 0; ci < 32; ci++) {
        if (ci + 1 < 32) { FILL_CHUNK(ci + 1, (ci + 1) & 1); CP_WAIT1(); }
        else             { CP_WAIT0(); }
        __syncthreads();

        const __half* xs = sm1 + (ci & 1) * STG_H;
        const __half* ws = xs + XS_H;

        for (int ti = 0; ti < ntap; ti++) {
            int coff = c_tdy[par][ti] * 68 + c_tdx[par][ti];
            uint32_t breg[4][2];
#pragma unroll
            for (int ni = 0; ni < 4; ni++) {
                const uint32_t* pB =
                    (const uint32_t*)&xs[(bcell[ni] + coff) * 24 + 2 * tig];
                breg[ni][0] = pB[0];
                breg[ni][1] = pB[4];
            }
#pragma unroll
            for (int mi = 0; mi < 4; mi++) {
                const uint32_t* pA = (const uint32_t*)
                    &ws[(ti * 128 + warp_m * 64 + mi * 16 + grp) * 24 + 2 * tig];
                uint32_t a0 = pA[0], a2 = pA[4];
                uint32_t a1 = pA[96], a3 = pA[100];   // +8 co rows
#pragma unroll
                for (int ni = 0; ni < 4; ni++)
                    mma16816(acc[mi][ni], a0, a1, a2, a3,
                             breg[ni][0], breg[ni][1]);
            }
        }
        __syncthreads();
    }

    // ---- store z: pair-interleaved [b][par][n>>1][co][2], half2 per (f0,f1)
    __half2* zpp = (__half2*)(g_z + ((size_t)(b * 4 + par)) * 2240 * 512);
#pragma unroll
    for (int mi = 0; mi < 4; mi++) {
        int coA = co0 + warp_m * 64 + mi * 16 + grp;
#pragma unroll
        for (int ni = 0; ni < 4; ni++) {
            int n = n0 + warp_n * 32 + ni * 8 + 2 * tig;   // even
            if (n < 4356) {
                size_t base = (size_t)(n >> 1) * 256;
                float* f = acc[mi][ni];
                zpp[base + coA] =
                    __halves2half2(__float2half_rn(f[0]), __float2half_rn(f[1]));
                zpp[base + coA + 8] =
                    __halves2half2(__float2half_rn(f[2]), __float2half_rn(f[3]));
            }
        }
    }
#undef FILL_CHUNK
}

// ---------------------------- stage2: separable FIR + epilogue -------------
// grid (64 = 8x8 tiles of 16x16 px, 8 co-groups of 32, 8 b), 256 threads.
// smem: zt[400 cells][33] fp32 (4 par x 10 x 10), hs[16 px][19 zy][33] fp32.
#define HS_OFF 13200
#define S2_SMEM ((13200 + 16 * 19 * 33) * 4)    // 92928 B

__global__ __launch_bounds__(256) void stage2(const float* __restrict__ bias,
                                              const float* __restrict__ noise,
                                              const float* __restrict__ nstr,
                                              float* __restrict__ out) {
    extern __shared__ float s2[];
    float* zt = s2;
    float* hs = s2 + HS_OFF;

    int bx = blockIdx.x;
    int my0 = (bx >> 3) * 16, mx0 = (bx & 7) * 16;
    int P0 = my0 >> 1, Q0 = mx0 >> 1;
    int co0 = blockIdx.y * 32, b = blockIdx.z;
    int tid = threadIdx.x;

    // fill zt (coalesced over co)
    const __half* zsrc = g_z + (size_t)(b * 4) * 2240 * 512;
    for (int u = tid; u < 12800; u += 256) {
        int co_l = u & 31, cell = u >> 5;
        int par = cell / 100, rem = cell % 100;
        int ys = rem / 10, xq = rem % 10;
        int n = (P0 + ys) * 66 + Q0 + xq;
        zt[cell * 33 + co_l] = __half2float(
            zsrc[((size_t)par * 2240 + (n >> 1)) * 512 + (co0 + co_l) * 2 +
                 (n & 1)]);
    }
    __syncthreads();

    // horizontal pass: hs[px][zyl][co] = sum_kx c4[kx] * z[my0+zyl][mx0+px+kx]
    const float C4[4] = {0.25f, 0.75f, 0.75f, 0.25f};
    for (int i = 0; i < 38; i++) {
        int u = i * 256 + tid;
        if (u < 9728) {
            int co_l = u & 31, rem = u >> 5;     // 0..303
            int zyl = rem >> 4, px = rem & 15;   // zyl 0..18
            int pary = (zyl & 1) * 2, pl = zyl >> 1;
            float a = 0.f;
#pragma unroll
            for (int kx = 0; kx < 4; kx++) {
                int zxl = px + kx;
                int cell = ((pary + (zxl & 1)) * 10 + pl) * 10 + (zxl >> 1);
                a += C4[kx] * zt[cell * 33 + co_l];
            }
            hs[(px * 19 + zyl) * 33 + co_l] = a;
        }
    }
    __syncthreads();

    // vertical pass + epilogue: thread = (px, co pair)
    float ns = *nstr;
    int px = tid & 15, cg = tid >> 4;
    int coA = co0 + 2 * cg;
    float bv0 = bias[coA], bv1 = bias[coA + 1];
    float* op0 = out + ((size_t)(b * 256 + coA) * 128 + my0) * 128 + mx0 + px;
    float* op1 = op0 + 16384;
    const float* np = noise + my0 * 128 + mx0 + px;

#pragma unroll
    for (int py = 0; py < 16; py++) {
        float s0 = 0.f, s1 = 0.f;
#pragma unroll
        for (int ky = 0; ky < 4; ky++) {
            int r = (px * 19 + py + ky) * 33 + 2 * cg;
            s0 += C4[ky] * hs[r];
            s1 += C4[ky] * hs[r + 1];
        }
        float nz = np[py * 128] * ns;
        float v0 = s0 + nz + bv0;
        float v1 = s1 + nz + bv1;
        v0 = (v0 >= 0.f ? v0 : 0.2f * v0) * 1.41421356237309515f;
        v1 = (v1 >= 0.f ? v1 : 0.2f * v1) * 1.41421356237309515f;
        op0[py * 128] = v0;
        op1[py * 128] = v1;
    }
}

// ---------------------------------------------------------------------------
extern "C" void kernel_launch(void* const* d_in, const int* in_sizes, int n_in,
                              void* d_out, int out_size) {
    (void)in_sizes; (void)n_in; (void)out_size;
    const float* x     = (const float*)d_in[0];   // [8,512,64,64]
    const float* w     = (const float*)d_in[1];   // [256,512,3,3]
    const float* bias  = (const float*)d_in[2];   // [256]
    const float* noise = (const float*)d_in[3];   // [128,128]
    const float* nstr  = (const float*)d_in[4];   // scalar
    float* out = (float*)d_out;                   // [8,256,128,128]

    cudaFuncSetAttribute(stage1, cudaFuncAttributeMaxDynamicSharedMemorySize,
                         S1_SMEM);
    cudaFuncSetAttribute(stage2, cudaFuncAttributeMaxDynamicSharedMemorySize,
                         S2_SMEM);

    prep_weights<<<256, 256>>>(w);
    dim3 gx(74, 8);
    prep_x<<<gx, 8 * 32>>>(x);

    dim3 g1(35, 8, 8);          // 35 flattened-n tiles, par*2+cohalf, batches
    stage1<<<g1, 256, S1_SMEM>>>();

    dim3 g2(64, 8, 8);
    stage2<<<g2, 256, S2_SMEM>>>(bias, noise, nstr, out);
}

// round 14
// speedup vs baseline: 5.1168x; 1.0363x over previous
#include <cuda_runtime.h>
#include <cuda_fp16.h>
#include <stdint.h>
#include <math.h>

// ---------------------------------------------------------------------------
// StyleGAN2 up-2x synthesis layer (mma.sync; tcgen05 not available on this
// ptxas target):
//   prep_w : L2-normalize + flip -> g_whh[tap][co][cin] fp16
//   prep_x : NCHW fp32 -> NHWC fp16 halo buffer g_xh2[b][74][68][512]
//   stage1 : 4 parity GEMMs, N = flattened spatial n=p*66+q (35 tiles of 128),
//            CTA = 128co x 128n, cp.async double buffer, occ 2.
//            z fp16 pair-interleaved [b][par][n>>1][co][2]
//   stage2 : 4x4 separable FIR with register-resident h-pass (no hs smem),
//            + noise + bias + lrelu*sqrt2
// ---------------------------------------------------------------------------

__device__ __half g_whh[9 * 256 * 512];                    // [tap][co][cin]
__device__ __half g_xh2[(size_t)8 * 74 * 68 * 512];        // [b][y][x'][cin]
__device__ __half g_z[(size_t)8 * 4 * 2240 * 512];         // [b][par][n/2][co][2]

__constant__ int c_ntap[4]     = {1, 2, 2, 4};
__constant__ int c_tapid[4][4] = {{4,0,0,0},{3,5,0,0},{1,7,0,0},{0,2,6,8}};
__constant__ int c_tdy[4][4]   = {{0,0,0,0},{0,0,0,0},{0,1,0,0},{0,0,1,1}};
__constant__ int c_tdx[4][4]   = {{0,0,0,0},{0,1,0,0},{0,0,0,0},{0,1,0,1}};

#define CP16(d, s) asm volatile("cp.async.cg.shared.global [%0], [%1], 16;" :: "r"(d), "l"(s))
#define CP_COMMIT() asm volatile("cp.async.commit_group;" ::: "memory")
#define CP_WAIT1()  asm volatile("cp.async.wait_group 1;" ::: "memory")
#define CP_WAIT0()  asm volatile("cp.async.wait_group 0;" ::: "memory")

static __device__ __forceinline__ uint32_t smem_u32(const void* p) {
    uint32_t a;
    asm("{ .reg .u64 t; cvta.to.shared.u64 t, %1; cvt.u32.u64 %0, t; }"
        : "=r"(a) : "l"(p));
    return a;
}

__device__ __forceinline__ void mma16816(float* d, uint32_t a0, uint32_t a1,
                                         uint32_t a2, uint32_t a3,
                                         uint32_t b0, uint32_t b1) {
    asm volatile(
        "mma.sync.aligned.m16n8k16.row.col.f32.f16.f16.f32 "
        "{%0,%1,%2,%3}, {%4,%5,%6,%7}, {%8,%9}, {%0,%1,%2,%3};\n"
        : "+f"(d[0]), "+f"(d[1]), "+f"(d[2]), "+f"(d[3])
        : "r"(a0), "r"(a1), "r"(a2), "r"(a3), "r"(b0), "r"(b1));
}

// ---------------------------- prep_weights ---------------------------------
__global__ void prep_weights(const float* __restrict__ w) {
    int co = blockIdx.x, tid = threadIdx.x;
    const float* wc = w + (size_t)co * 4608;
    float s = 0.f;
    for (int i = tid; i < 4608; i += 256) { float v = wc[i]; s += v * v; }
    __shared__ float red[256];
    red[tid] = s; __syncthreads();
    for (int off = 128; off > 0; off >>= 1) {
        if (tid < off) red[tid] += red[tid + off];
        __syncthreads();
    }
    float inv = rsqrtf(red[0] + 1e-8f);
    for (int i = tid; i < 4608; i += 256) {
        int cin = i / 9, r = i % 9, ty = r / 3, tx = r % 3;
        float v = wc[cin * 9 + (2 - ty) * 3 + (2 - tx)] * inv;
        g_whh[((size_t)r * 256 + co) * 512 + cin] = __float2half_rn(v);
    }
}

// ---------------------------- prep_x (NCHW->NHWC halo) ---------------------
__global__ void prep_x(const float* __restrict__ x) {
    int gy = blockIdx.x, b = blockIdx.y, tid = threadIdx.x;   // gy in [0,74)
    __half2* dst = (__half2*)(g_xh2 + ((size_t)(b * 74 + gy)) * 68 * 512);
    if (gy == 0 || gy >= 65) {
        __half2 z = __halves2half2(__float2half_rn(0.f), __float2half_rn(0.f));
        for (int u = tid; u < 68 * 256; u += 256) dst[u] = z;
        return;
    }
    __shared__ __half sm[256 * 66];
    const float* src = x + (size_t)b * 512 * 4096 + (gy - 1) * 64;
    for (int h = 0; h < 2; h++) {
        for (int u = tid; u < 256 * 64; u += 256) {
            int cl = u >> 6, xx = u & 63;
            sm[cl * 66 + xx] =
                __float2half_rn(src[(size_t)(256 * h + cl) * 4096 + xx]);
        }
        __syncthreads();
        for (int u = tid; u < 68 * 128; u += 256) {
            int xp = u >> 7, cpl = u & 127;
            int cp = 128 * h + cpl;
            __half2 v;
            if (xp >= 1 && xp < 65)
                v = __halves2half2(sm[(2 * cpl) * 66 + xp - 1],
                                   sm[(2 * cpl + 1) * 66 + xp - 1]);
            else
                v = __halves2half2(__float2half_rn(0.f), __float2half_rn(0.f));
            dst[xp * 256 + cp] = v;
        }
        __syncthreads();
    }
}

// ---------------------------- stage1: parity GEMMs -------------------------
// grid (35 n-tiles, par*2+cohalf, b), 256 threads, occ 2.
#define KC 16
#define XS_H (272 * 24)                 // 4 rows x 68 cols cells, stride 24
#define WS_H (4 * 128 * 24)
#define STG_H (XS_H + WS_H)             // 18816 halves
#define S1_SMEM (2 * STG_H * 2)         // 75264 B

__global__ __launch_bounds__(256, 2) void stage1() {
    extern __shared__ __align__(16) __half sm1[];

    int n0 = blockIdx.x * 128;
    int p_lo = n0 / 66;
    int par = blockIdx.y >> 1;
    int co0 = (blockIdx.y & 1) * 128;
    int b   = blockIdx.z;
    int ntap = c_ntap[par];
    int ncp  = 544 + ntap * 256;

    int tid = threadIdx.x, lane = tid & 31, wid = tid >> 5;
    int warp_m = wid & 1;
    int warp_n = wid >> 1;
    int tig = lane & 3, grp = lane >> 2;

    const __half* xh = g_xh2 + (size_t)b * 74 * 68 * 512;

    int bcell[4];
#pragma unroll
    for (int ni = 0; ni < 4; ni++) {
        int n = n0 + warp_n * 32 + ni * 8 + grp;
        int p = n / 66, q = n - p * 66;
        bcell[ni] = (p - p_lo) * 68 + q;
    }

    float acc[4][4][4];
#pragma unroll
    for (int i = 0; i < 4; i++)
#pragma unroll
        for (int j = 0; j < 4; j++)
#pragma unroll
            for (int k = 0; k < 4; k++) acc[i][j][k] = 0.f;

    uint32_t sbase = smem_u32(sm1);

#define FILL_CHUNK(CI, S)                                                      \
    do {                                                                       \
        int _c0 = (CI) * KC;                                                   \
        uint32_t _xs = sbase + (S) * (STG_H * 2);                              \
        uint32_t _ws = _xs + XS_H * 2;                                         \
        for (int u = tid; u < ncp; u += 256) {                                 \
            const __half* src;                                                 \
            uint32_t dst;                                                      \
            if (u < 544) {                                                     \
                int r = u / 136, rem2 = u % 136;                               \
                int colx = rem2 >> 1, seg = rem2 & 1;                          \
                src = xh + ((size_t)((p_lo + r) * 68 + colx)) * 512 + _c0 +    \
                      seg * 8;                                                 \
                dst = _xs + ((r * 68 + colx) * 24 + seg * 8) * 2;              \
            } else {                                                           \
                int v = u - 544;                                               \
                int ti = v >> 8, r8 = v & 255, co = r8 >> 1, seg = r8 & 1;     \
                src = g_whh + ((size_t)c_tapid[par][ti] * 256 + co0 + co) *    \
                          512 + _c0 + seg * 8;                                 \
                dst = _ws + ((ti * 128 + co) * 24 + seg * 8) * 2;              \
            }                                                                  \
            CP16(dst, src);                                                    \
        }                                                                      \
        CP_COMMIT();                                                           \
    } while (0)

    FILL_CHUNK(0, 0);

    for (int ci = 0; ci < 32; ci++) {
        if (ci + 1 < 32) { FILL_CHUNK(ci + 1, (ci + 1) & 1); CP_WAIT1(); }
        else             { CP_WAIT0(); }
        __syncthreads();

        const __half* xs = sm1 + (ci & 1) * STG_H;
        const __half* ws = xs + XS_H;

        for (int ti = 0; ti < ntap; ti++) {
            int coff = c_tdy[par][ti] * 68 + c_tdx[par][ti];
            uint32_t breg[4][2];
#pragma unroll
            for (int ni = 0; ni < 4; ni++) {
                const uint32_t* pB =
                    (const uint32_t*)&xs[(bcell[ni] + coff) * 24 + 2 * tig];
                breg[ni][0] = pB[0];
                breg[ni][1] = pB[4];
            }
#pragma unroll
            for (int mi = 0; mi < 4; mi++) {
                const uint32_t* pA = (const uint32_t*)
                    &ws[(ti * 128 + warp_m * 64 + mi * 16 + grp) * 24 + 2 * tig];
                uint32_t a0 = pA[0], a2 = pA[4];
                uint32_t a1 = pA[96], a3 = pA[100];
#pragma unroll
                for (int ni = 0; ni < 4; ni++)
                    mma16816(acc[mi][ni], a0, a1, a2, a3,
                             breg[ni][0], breg[ni][1]);
            }
        }
        __syncthreads();
    }

    __half2* zpp = (__half2*)(g_z + ((size_t)(b * 4 + par)) * 2240 * 512);
#pragma unroll
    for (int mi = 0; mi < 4; mi++) {
        int coA = co0 + warp_m * 64 + mi * 16 + grp;
#pragma unroll
        for (int ni = 0; ni < 4; ni++) {
            int n = n0 + warp_n * 32 + ni * 8 + 2 * tig;   // even
            if (n < 4356) {
                size_t base = (size_t)(n >> 1) * 256;
                float* f = acc[mi][ni];
                zpp[base + coA] =
                    __halves2half2(__float2half_rn(f[0]), __float2half_rn(f[1]));
                zpp[base + coA + 8] =
                    __halves2half2(__float2half_rn(f[2]), __float2half_rn(f[3]));
            }
        }
    }
#undef FILL_CHUNK
}

// ---------------------------- stage2: FIR + epilogue -----------------------
// grid (64 = 8x8 tiles of 16x16 px, 8 co-groups of 32, 8 b), 256 threads.
// smem: zt[400 cells][33] fp32 only (52.8KB -> 4 CTAs/SM). h-pass lives in
// registers per thread (19 values x 2 co).
#define S2_SMEM (13200 * 4)

__global__ __launch_bounds__(256) void stage2(const float* __restrict__ bias,
                                              const float* __restrict__ noise,
                                              const float* __restrict__ nstr,
                                              float* __restrict__ out) {
    extern __shared__ float zt[];      // [cell(4par x 10pl x 10q)][33]

    int bx = blockIdx.x;
    int my0 = (bx >> 3) * 16, mx0 = (bx & 7) * 16;
    int P0 = my0 >> 1, Q0 = mx0 >> 1;
    int co0 = blockIdx.y * 32, b = blockIdx.z;
    int tid = threadIdx.x;

    // fill zt (coalesced over co)
    const __half* zsrc = g_z + (size_t)(b * 4) * 2240 * 512;
    for (int u = tid; u < 12800; u += 256) {
        int co_l = u & 31, cell = u >> 5;
        int par = cell / 100, rem = cell % 100;
        int ys = rem / 10, xq = rem % 10;
        int n = (P0 + ys) * 66 + Q0 + xq;
        zt[cell * 33 + co_l] = __half2float(
            zsrc[((size_t)par * 2240 + (n >> 1)) * 512 + (co0 + co_l) * 2 +
                 (n & 1)]);
    }
    __syncthreads();

    // thread = (px, co pair). h-pass into registers, v-pass from registers.
    const float C4[4] = {0.25f, 0.75f, 0.75f, 0.25f};
    int px = tid & 15, cg = tid >> 4;
    int c0l = 2 * cg;

    // per-kx cell offset within a pary-slab: offkx = (zxl&1)*100 + (zxl>>1)
    int offkx[4];
#pragma unroll
    for (int kx = 0; kx < 4; kx++) {
        int zxl = px + kx;
        offkx[kx] = (zxl & 1) * 100 + (zxl >> 1);
    }

    float h0[19], h1[19];
#pragma unroll
    for (int zyl = 0; zyl < 19; zyl++) {
        int base = ((zyl & 1) * 2) * 100 + (zyl >> 1) * 10;   // pary slab + pl row
        float a0 = 0.f, a1 = 0.f;
#pragma unroll
        for (int kx = 0; kx < 4; kx++) {
            const float* p = &zt[(base + offkx[kx]) * 33 + c0l];
            a0 += C4[kx] * p[0];
            a1 += C4[kx] * p[1];
        }
        h0[zyl] = a0;
        h1[zyl] = a1;
    }

    float ns = *nstr;
    int coA = co0 + c0l;
    float bv0 = bias[coA], bv1 = bias[coA + 1];
    float* op0 = out + ((size_t)(b * 256 + coA) * 128 + my0) * 128 + mx0 + px;
    float* op1 = op0 + 16384;
    const float* np = noise + my0 * 128 + mx0 + px;

#pragma unroll
    for (int py = 0; py < 16; py++) {
        float s0 = C4[0] * h0[py] + C4[1] * h0[py + 1] + C4[2] * h0[py + 2] +
                   C4[3] * h0[py + 3];
        float s1 = C4[0] * h1[py] + C4[1] * h1[py + 1] + C4[2] * h1[py + 2] +
                   C4[3] * h1[py + 3];
        float nz = np[py * 128] * ns;
        float v0 = s0 + nz + bv0;
        float v1 = s1 + nz + bv1;
        v0 = (v0 >= 0.f ? v0 : 0.2f * v0) * 1.41421356237309515f;
        v1 = (v1 >= 0.f ? v1 : 0.2f * v1) * 1.41421356237309515f;
        op0[py * 128] = v0;
        op1[py * 128] = v1;
    }
}

// ---------------------------------------------------------------------------
extern "C" void kernel_launch(void* const* d_in, const int* in_sizes, int n_in,
                              void* d_out, int out_size) {
    (void)in_sizes; (void)n_in; (void)out_size;
    const float* x     = (const float*)d_in[0];   // [8,512,64,64]
    const float* w     = (const float*)d_in[1];   // [256,512,3,3]
    const float* bias  = (const float*)d_in[2];   // [256]
    const float* noise = (const float*)d_in[3];   // [128,128]
    const float* nstr  = (const float*)d_in[4];   // scalar
    float* out = (float*)d_out;                   // [8,256,128,128]

    cudaFuncSetAttribute(stage1, cudaFuncAttributeMaxDynamicSharedMemorySize,
                         S1_SMEM);
    cudaFuncSetAttribute(stage2, cudaFuncAttributeMaxDynamicSharedMemorySize,
                         S2_SMEM);

    prep_weights<<<256, 256>>>(w);
    dim3 gx(74, 8);
    prep_x<<<gx, 256>>>(x);

    dim3 g1(35, 8, 8);
    stage1<<<g1, 256, S1_SMEM>>>();

    dim3 g2(64, 8, 8);
    stage2<<<g2, 256, S2_SMEM>>>(bias, noise, nstr, out);
}

// round 15
// speedup vs baseline: 5.6550x; 1.1052x over previous
#include <cuda_runtime.h>
#include <cuda_fp16.h>
#include <stdint.h>
#include <math.h>

// ---------------------------------------------------------------------------
// StyleGAN2 up-2x synthesis layer (mma.sync; tcgen05 not available on this
// ptxas target):
//   prep_w : L2-normalize + flip -> g_whh[tap][co][cin] fp16
//   prep_x : NCHW fp32 -> NHWC fp16 halo buffer g_xh2[b][74][68][512]
//   stage1 : 4 parity GEMMs, N = flattened spatial n=p*66+q (35 tiles of 128),
//            CTA = 128co x 128n, cp.async double buffer, occ 2.
//            z fp16 pair-interleaved [b][par][n>>1][co][2]
//   stage2 : 4x4 separable FIR, streaming register window (no h arrays, no
//            spills), incremental fill indexing + noise + bias + lrelu*sqrt2
// ---------------------------------------------------------------------------

__device__ __half g_whh[9 * 256 * 512];                    // [tap][co][cin]
__device__ __half g_xh2[(size_t)8 * 74 * 68 * 512];        // [b][y][x'][cin]
__device__ __half g_z[(size_t)8 * 4 * 2240 * 512];         // [b][par][n/2][co][2]

__constant__ int c_ntap[4]     = {1, 2, 2, 4};
__constant__ int c_tapid[4][4] = {{4,0,0,0},{3,5,0,0},{1,7,0,0},{0,2,6,8}};
__constant__ int c_tdy[4][4]   = {{0,0,0,0},{0,0,0,0},{0,1,0,0},{0,0,1,1}};
__constant__ int c_tdx[4][4]   = {{0,0,0,0},{0,1,0,0},{0,0,0,0},{0,1,0,1}};

#define CP16(d, s) asm volatile("cp.async.cg.shared.global [%0], [%1], 16;" :: "r"(d), "l"(s))
#define CP_COMMIT() asm volatile("cp.async.commit_group;" ::: "memory")
#define CP_WAIT1()  asm volatile("cp.async.wait_group 1;" ::: "memory")
#define CP_WAIT0()  asm volatile("cp.async.wait_group 0;" ::: "memory")

static __device__ __forceinline__ uint32_t smem_u32(const void* p) {
    uint32_t a;
    asm("{ .reg .u64 t; cvta.to.shared.u64 t, %1; cvt.u32.u64 %0, t; }"
        : "=r"(a) : "l"(p));
    return a;
}

__device__ __forceinline__ void mma16816(float* d, uint32_t a0, uint32_t a1,
                                         uint32_t a2, uint32_t a3,
                                         uint32_t b0, uint32_t b1) {
    asm volatile(
        "mma.sync.aligned.m16n8k16.row.col.f32.f16.f16.f32 "
        "{%0,%1,%2,%3}, {%4,%5,%6,%7}, {%8,%9}, {%0,%1,%2,%3};\n"
        : "+f"(d[0]), "+f"(d[1]), "+f"(d[2]), "+f"(d[3])
        : "r"(a0), "r"(a1), "r"(a2), "r"(a3), "r"(b0), "r"(b1));
}

// ---------------------------- prep_weights ---------------------------------
__global__ void prep_weights(const float* __restrict__ w) {
    int co = blockIdx.x, tid = threadIdx.x;
    const float* wc = w + (size_t)co * 4608;
    float s = 0.f;
    for (int i = tid; i < 4608; i += 256) { float v = wc[i]; s += v * v; }
    __shared__ float red[256];
    red[tid] = s; __syncthreads();
    for (int off = 128; off > 0; off >>= 1) {
        if (tid < off) red[tid] += red[tid + off];
        __syncthreads();
    }
    float inv = rsqrtf(red[0] + 1e-8f);
    for (int i = tid; i < 4608; i += 256) {
        int cin = i / 9, r = i % 9, ty = r / 3, tx = r % 3;
        float v = wc[cin * 9 + (2 - ty) * 3 + (2 - tx)] * inv;
        g_whh[((size_t)r * 256 + co) * 512 + cin] = __float2half_rn(v);
    }
}

// ---------------------------- prep_x (NCHW->NHWC halo) ---------------------
__global__ void prep_x(const float* __restrict__ x) {
    int gy = blockIdx.x, b = blockIdx.y, tid = threadIdx.x;   // gy in [0,74)
    __half2* dst = (__half2*)(g_xh2 + ((size_t)(b * 74 + gy)) * 68 * 512);
    if (gy == 0 || gy >= 65) {
        __half2 z = __halves2half2(__float2half_rn(0.f), __float2half_rn(0.f));
        for (int u = tid; u < 68 * 256; u += 256) dst[u] = z;
        return;
    }
    __shared__ __half sm[256 * 66];
    const float* src = x + (size_t)b * 512 * 4096 + (gy - 1) * 64;
    for (int h = 0; h < 2; h++) {
        for (int u = tid; u < 256 * 64; u += 256) {
            int cl = u >> 6, xx = u & 63;
            sm[cl * 66 + xx] =
                __float2half_rn(src[(size_t)(256 * h + cl) * 4096 + xx]);
        }
        __syncthreads();
        for (int u = tid; u < 68 * 128; u += 256) {
            int xp = u >> 7, cpl = u & 127;
            int cp = 128 * h + cpl;
            __half2 v;
            if (xp >= 1 && xp < 65)
                v = __halves2half2(sm[(2 * cpl) * 66 + xp - 1],
                                   sm[(2 * cpl + 1) * 66 + xp - 1]);
            else
                v = __halves2half2(__float2half_rn(0.f), __float2half_rn(0.f));
            dst[xp * 256 + cp] = v;
        }
        __syncthreads();
    }
}

// ---------------------------- stage1: parity GEMMs -------------------------
// grid (35 n-tiles, par*2+cohalf, b), 256 threads, occ 2.
#define KC 16
#define XS_H (272 * 24)                 // 4 rows x 68 cols cells, stride 24
#define WS_H (4 * 128 * 24)
#define STG_H (XS_H + WS_H)             // 18816 halves
#define S1_SMEM (2 * STG_H * 2)         // 75264 B

__global__ __launch_bounds__(256, 2) void stage1() {
    extern __shared__ __align__(16) __half sm1[];

    int n0 = blockIdx.x * 128;
    int p_lo = n0 / 66;
    int par = blockIdx.y >> 1;
    int co0 = (blockIdx.y & 1) * 128;
    int b   = blockIdx.z;
    int ntap = c_ntap[par];
    int ncp  = 544 + ntap * 256;

    int tid = threadIdx.x, lane = tid & 31, wid = tid >> 5;
    int warp_m = wid & 1;
    int warp_n = wid >> 1;
    int tig = lane & 3, grp = lane >> 2;

    const __half* xh = g_xh2 + (size_t)b * 74 * 68 * 512;

    int bcell[4];
#pragma unroll
    for (int ni = 0; ni < 4; ni++) {
        int n = n0 + warp_n * 32 + ni * 8 + grp;
        int p = n / 66, q = n - p * 66;
        bcell[ni] = (p - p_lo) * 68 + q;
    }

    float acc[4][4][4];
#pragma unroll
    for (int i = 0; i < 4; i++)
#pragma unroll
        for (int j = 0; j < 4; j++)
#pragma unroll
            for (int k = 0; k < 4; k++) acc[i][j][k] = 0.f;

    uint32_t sbase = smem_u32(sm1);

#define FILL_CHUNK(CI, S)                                                      \
    do {                                                                       \
        int _c0 = (CI) * KC;                                                   \
        uint32_t _xs = sbase + (S) * (STG_H * 2);                              \
        uint32_t _ws = _xs + XS_H * 2;                                         \
        for (int u = tid; u < ncp; u += 256) {                                 \
            const __half* src;                                                 \
            uint32_t dst;                                                      \
            if (u < 544) {                                                     \
                int r = u / 136, rem2 = u % 136;                               \
                int colx = rem2 >> 1, seg = rem2 & 1;                          \
                src = xh + ((size_t)((p_lo + r) * 68 + colx)) * 512 + _c0 +    \
                      seg * 8;                                                 \
                dst = _xs + ((r * 68 + colx) * 24 + seg * 8) * 2;              \
            } else {                                                           \
                int v = u - 544;                                               \
                int ti = v >> 8, r8 = v & 255, co = r8 >> 1, seg = r8 & 1;     \
                src = g_whh + ((size_t)c_tapid[par][ti] * 256 + co0 + co) *    \
                          512 + _c0 + seg * 8;                                 \
                dst = _ws + ((ti * 128 + co) * 24 + seg * 8) * 2;              \
            }                                                                  \
            CP16(dst, src);                                                    \
        }                                                                      \
        CP_COMMIT();                                                           \
    } while (0)

    FILL_CHUNK(0, 0);

    for (int ci = 0; ci < 32; ci++) {
        if (ci + 1 < 32) { FILL_CHUNK(ci + 1, (ci + 1) & 1); CP_WAIT1(); }
        else             { CP_WAIT0(); }
        __syncthreads();

        const __half* xs = sm1 + (ci & 1) * STG_H;
        const __half* ws = xs + XS_H;

        for (int ti = 0; ti < ntap; ti++) {
            int coff = c_tdy[par][ti] * 68 + c_tdx[par][ti];
            uint32_t breg[4][2];
#pragma unroll
            for (int ni = 0; ni < 4; ni++) {
                const uint32_t* pB =
                    (const uint32_t*)&xs[(bcell[ni] + coff) * 24 + 2 * tig];
                breg[ni][0] = pB[0];
                breg[ni][1] = pB[4];
            }
#pragma unroll
            for (int mi = 0; mi < 4; mi++) {
                const uint32_t* pA = (const uint32_t*)
                    &ws[(ti * 128 + warp_m * 64 + mi * 16 + grp) * 24 + 2 * tig];
                uint32_t a0 = pA[0], a2 = pA[4];
                uint32_t a1 = pA[96], a3 = pA[100];
#pragma unroll
                for (int ni = 0; ni < 4; ni++)
                    mma16816(acc[mi][ni], a0, a1, a2, a3,
                             breg[ni][0], breg[ni][1]);
            }
        }
        __syncthreads();
    }

    __half2* zpp = (__half2*)(g_z + ((size_t)(b * 4 + par)) * 2240 * 512);
#pragma unroll
    for (int mi = 0; mi < 4; mi++) {
        int coA = co0 + warp_m * 64 + mi * 16 + grp;
#pragma unroll
        for (int ni = 0; ni < 4; ni++) {
            int n = n0 + warp_n * 32 + ni * 8 + 2 * tig;   // even
            if (n < 4356) {
                size_t base = (size_t)(n >> 1) * 256;
                float* f = acc[mi][ni];
                zpp[base + coA] =
                    __halves2half2(__float2half_rn(f[0]), __float2half_rn(f[1]));
                zpp[base + coA + 8] =
                    __halves2half2(__float2half_rn(f[2]), __float2half_rn(f[3]));
            }
        }
    }
#undef FILL_CHUNK
}

// ---------------------------- stage2: FIR + epilogue -----------------------
// grid (64 = 8x8 tiles of 16x16 px, 8 co-groups of 32, 8 b), 256 threads.
// smem: zt[400 cells][33] fp32 (52.8KB -> 4 CTAs/SM). h-pass is a streaming
// 4-deep register window per (px, co-pair); fill uses incremental indexing.
#define S2_SMEM (13200 * 4)

__global__ __launch_bounds__(256) void stage2(const float* __restrict__ bias,
                                              const float* __restrict__ noise,
                                              const float* __restrict__ nstr,
                                              float* __restrict__ out) {
    extern __shared__ float zt[];      // [cell(4par x 10pl x 10q)][33]

    int bx = blockIdx.x;
    int my0 = (bx >> 3) * 16, mx0 = (bx & 7) * 16;
    int P0 = my0 >> 1, Q0 = mx0 >> 1;
    int co0 = blockIdx.y * 32, b = blockIdx.z;
    int tid = threadIdx.x;

    // ---- fill zt: co_l fixed per thread; cell advances by 8 per iteration,
    // (par, ys, xq, n) maintained incrementally (no div/mod, no mul66).
    {
        const __half* zsrc = g_z + (size_t)(b * 4) * 2240 * 512;
        int co_l = tid & 31;
        int cell = tid >> 5;                    // 0..7
        int ys = 0, xq = cell, par = 0;
        int n = P0 * 66 + Q0 + xq;
        int col2 = (co0 + co_l) * 2;
#pragma unroll 5
        for (int i = 0; i < 50; i++) {
            zt[cell * 33 + co_l] = __half2float(
                zsrc[(((size_t)par * 2240 + (n >> 1)) << 9) + col2 + (n & 1)]);
            cell += 8;
            xq += 8; n += 8;
            if (xq >= 10) {
                xq -= 10; ys += 1; n += 56;     // -10 cols + 1 row(66)
                if (ys >= 10) { ys -= 10; par += 1; n -= 660; }
            }
        }
    }
    __syncthreads();

    // ---- streaming separable FIR: h window of 4 per co (no arrays/spills)
    const float C4[4] = {0.25f, 0.75f, 0.75f, 0.25f};
    int px = tid & 15, cg = tid >> 4;
    int c0l = 2 * cg;

    // full smem float-offsets per kx (incl. *33 and +c0l)
    int offk[4];
#pragma unroll
    for (int kx = 0; kx < 4; kx++) {
        int zxl = px + kx;
        offk[kx] = ((zxl & 1) * 100 + (zxl >> 1)) * 33 + c0l;
    }

    float ns = *nstr;
    int coA = co0 + c0l;
    float bv0 = bias[coA], bv1 = bias[coA + 1];
    float* op0 = out + ((size_t)(b * 256 + coA) * 128 + my0) * 128 + mx0 + px;
    float* op1 = op0 + 16384;
    const float* np = noise + my0 * 128 + mx0 + px;

    float w0a = 0.f, w1a = 0.f, w2a = 0.f, w3a = 0.f;
    float w0b = 0.f, w1b = 0.f, w2b = 0.f, w3b = 0.f;

#pragma unroll
    for (int zyl = 0; zyl < 19; zyl++) {
        int base = (((zyl & 1) * 2) * 100 + (zyl >> 1) * 10) * 33;  // cexpr
        float a0 = 0.f, a1 = 0.f;
#pragma unroll
        for (int kx = 0; kx < 4; kx++) {
            const float* p = &zt[base + offk[kx]];
            a0 += C4[kx] * p[0];
            a1 += C4[kx] * p[1];
        }
        w0a = w1a; w1a = w2a; w2a = w3a; w3a = a0;
        w0b = w1b; w1b = w2b; w2b = w3b; w3b = a1;
        if (zyl >= 3) {
            int py = zyl - 3;
            float s0 = C4[0] * w0a + C4[1] * w1a + C4[2] * w2a + C4[3] * w3a;
            float s1 = C4[0] * w0b + C4[1] * w1b + C4[2] * w2b + C4[3] * w3b;
            float nz = np[py * 128] * ns;
            float v0 = s0 + nz + bv0;
            float v1 = s1 + nz + bv1;
            v0 = (v0 >= 0.f ? v0 : 0.2f * v0) * 1.41421356237309515f;
            v1 = (v1 >= 0.f ? v1 : 0.2f * v1) * 1.41421356237309515f;
            op0[py * 128] = v0;
            op1[py * 128] = v1;
        }
    }
}

// ---------------------------------------------------------------------------
extern "C" void kernel_launch(void* const* d_in, const int* in_sizes, int n_in,
                              void* d_out, int out_size) {
    (void)in_sizes; (void)n_in; (void)out_size;
    const float* x     = (const float*)d_in[0];   // [8,512,64,64]
    const float* w     = (const float*)d_in[1];   // [256,512,3,3]
    const float* bias  = (const float*)d_in[2];   // [256]
    const float* noise = (const float*)d_in[3];   // [128,128]
    const float* nstr  = (const float*)d_in[4];   // scalar
    float* out = (float*)d_out;                   // [8,256,128,128]

    cudaFuncSetAttribute(stage1, cudaFuncAttributeMaxDynamicSharedMemorySize,
                         S1_SMEM);
    cudaFuncSetAttribute(stage2, cudaFuncAttributeMaxDynamicSharedMemorySize,
                         S2_SMEM);

    prep_weights<<<256, 256>>>(w);
    dim3 gx(74, 8);
    prep_x<<<gx, 256>>>(x);

    dim3 g1(35, 8, 8);
    stage1<<<g1, 256, S1_SMEM>>>();

    dim3 g2(64, 8, 8);
    stage2<<<g2, 256, S2_SMEM>>>(bias, noise, nstr, out);
}

// round 17
// speedup vs baseline: 5.7364x; 1.0144x over previous
#include <cuda_runtime.h>
#include <cuda_fp16.h>
#include <stdint.h>
#include <math.h>

// ---------------------------------------------------------------------------
// StyleGAN2 up-2x synthesis layer (mma.sync; tcgen05 not available on this
// ptxas target):
//   prep_w : L2-normalize + flip -> g_whh[tap][co][cin] fp16
//   prep_x : NCHW fp32 -> NHWC fp16 halo buffer g_xh2[b][74][68][512]
//   stage1 : 4 parity GEMMs, N = flattened spatial n=p*66+q (35 tiles of 128),
//            CTA = 128co x 128n, cp.async double buffer, ONE sync per chunk.
//            z fp16 pair-interleaved [b][par][n>>1][co][2]
//   stage2 : 4x4 separable FIR, streaming register window; pair-word zt fill
//            (1 uint32 = 2 cells) + float2 h-pass LDS; noise+bias+lrelu*sqrt2
// ---------------------------------------------------------------------------

__device__ __half g_whh[9 * 256 * 512];                    // [tap][co][cin]
__device__ __half g_xh2[(size_t)8 * 74 * 68 * 512];        // [b][y][x'][cin]
__device__ __half g_z[(size_t)8 * 4 * 2240 * 512];         // [b][par][n/2][co][2]

__constant__ int c_ntap[4]     = {1, 2, 2, 4};
__constant__ int c_tapid[4][4] = {{4,0,0,0},{3,5,0,0},{1,7,0,0},{0,2,6,8}};
__constant__ int c_tdy[4][4]   = {{0,0,0,0},{0,0,0,0},{0,1,0,0},{0,0,1,1}};
__constant__ int c_tdx[4][4]   = {{0,0,0,0},{0,1,0,0},{0,0,0,0},{0,1,0,1}};

#define CP16(d, s) asm volatile("cp.async.cg.shared.global [%0], [%1], 16;" :: "r"(d), "l"(s))
#define CP_COMMIT() asm volatile("cp.async.commit_group;" ::: "memory")
#define CP_WAIT0()  asm volatile("cp.async.wait_group 0;" ::: "memory")

static __device__ __forceinline__ uint32_t smem_u32(const void* p) {
    uint32_t a;
    asm("{ .reg .u64 t; cvta.to.shared.u64 t, %1; cvt.u32.u64 %0, t; }"
        : "=r"(a) : "l"(p));
    return a;
}

__device__ __forceinline__ void mma16816(float* d, uint32_t a0, uint32_t a1,
                                         uint32_t a2, uint32_t a3,
                                         uint32_t b0, uint32_t b1) {
    asm volatile(
        "mma.sync.aligned.m16n8k16.row.col.f32.f16.f16.f32 "
        "{%0,%1,%2,%3}, {%4,%5,%6,%7}, {%8,%9}, {%0,%1,%2,%3};\n"
        : "+f"(d[0]), "+f"(d[1]), "+f"(d[2]), "+f"(d[3])
        : "r"(a0), "r"(a1), "r"(a2), "r"(a3), "r"(b0), "r"(b1));
}

// ---------------------------- prep_weights ---------------------------------
__global__ void prep_weights(const float* __restrict__ w) {
    int co = blockIdx.x, tid = threadIdx.x;
    const float* wc = w + (size_t)co * 4608;
    float s = 0.f;
    for (int i = tid; i < 4608; i += 256) { float v = wc[i]; s += v * v; }
    __shared__ float red[256];
    red[tid] = s; __syncthreads();
    for (int off = 128; off > 0; off >>= 1) {
        if (tid < off) red[tid] += red[tid + off];
        __syncthreads();
    }
    float inv = rsqrtf(red[0] + 1e-8f);
    for (int i = tid; i < 4608; i += 256) {
        int cin = i / 9, r = i % 9, ty = r / 3, tx = r % 3;
        float v = wc[cin * 9 + (2 - ty) * 3 + (2 - tx)] * inv;
        g_whh[((size_t)r * 256 + co) * 512 + cin] = __float2half_rn(v);
    }
}

// ---------------------------- prep_x (NCHW->NHWC halo) ---------------------
__global__ void prep_x(const float* __restrict__ x) {
    int gy = blockIdx.x, b = blockIdx.y, tid = threadIdx.x;   // gy in [0,74)
    __half2* dst = (__half2*)(g_xh2 + ((size_t)(b * 74 + gy)) * 68 * 512);
    if (gy == 0 || gy >= 65) {
        __half2 z = __halves2half2(__float2half_rn(0.f), __float2half_rn(0.f));
        for (int u = tid; u < 68 * 256; u += 256) dst[u] = z;
        return;
    }
    __shared__ __half sm[256 * 66];
    const float* src = x + (size_t)b * 512 * 4096 + (gy - 1) * 64;
    for (int h = 0; h < 2; h++) {
        for (int u = tid; u < 256 * 64; u += 256) {
            int cl = u >> 6, xx = u & 63;
            sm[cl * 66 + xx] =
                __float2half_rn(src[(size_t)(256 * h + cl) * 4096 + xx]);
        }
        __syncthreads();
        for (int u = tid; u < 68 * 128; u += 256) {
            int xp = u >> 7, cpl = u & 127;
            int cp = 128 * h + cpl;
            __half2 v;
            if (xp >= 1 && xp < 65)
                v = __halves2half2(sm[(2 * cpl) * 66 + xp - 1],
                                   sm[(2 * cpl + 1) * 66 + xp - 1]);
            else
                v = __halves2half2(__float2half_rn(0.f), __float2half_rn(0.f));
            dst[xp * 256 + cp] = v;
        }
        __syncthreads();
    }
}

// ---------------------------- stage1: parity GEMMs -------------------------
// grid (35 n-tiles, par*2+cohalf, b), 256 threads, occ 2. ONE sync per chunk:
//   WAIT0(fill ci) -> sync -> FILL(ci+1, other stage) -> compute(ci)
#define KC 16
#define XS_H (272 * 24)                 // 4 rows x 68 cols cells, stride 24
#define WS_H (4 * 128 * 24)
#define STG_H (XS_H + WS_H)             // 18816 halves
#define S1_SMEM (2 * STG_H * 2)         // 75264 B

__global__ __launch_bounds__(256, 2) void stage1() {
    extern __shared__ __align__(16) __half sm1[];

    int n0 = blockIdx.x * 128;
    int p_lo = n0 / 66;
    int par = blockIdx.y >> 1;
    int co0 = (blockIdx.y & 1) * 128;
    int b   = blockIdx.z;
    int ntap = c_ntap[par];
    int ncp  = 544 + ntap * 256;

    int tid = threadIdx.x, lane = tid & 31, wid = tid >> 5;
    int warp_m = wid & 1;
    int warp_n = wid >> 1;
    int tig = lane & 3, grp = lane >> 2;

    const __half* xh = g_xh2 + (size_t)b * 74 * 68 * 512;

    int bcell[4];
#pragma unroll
    for (int ni = 0; ni < 4; ni++) {
        int n = n0 + warp_n * 32 + ni * 8 + grp;
        int p = n / 66, q = n - p * 66;
        bcell[ni] = (p - p_lo) * 68 + q;
    }

    float acc[4][4][4];
#pragma unroll
    for (int i = 0; i < 4; i++)
#pragma unroll
        for (int j = 0; j < 4; j++)
#pragma unroll
            for (int k = 0; k < 4; k++) acc[i][j][k] = 0.f;

    uint32_t sbase = smem_u32(sm1);

#define FILL_CHUNK(CI, S)                                                      \
    do {                                                                       \
        int _c0 = (CI) * KC;                                                   \
        uint32_t _xs = sbase + (S) * (STG_H * 2);                              \
        uint32_t _ws = _xs + XS_H * 2;                                         \
        for (int u = tid; u < ncp; u += 256) {                                 \
            const __half* src;                                                 \
            uint32_t dst;                                                      \
            if (u < 544) {                                                     \
                int r = u / 136, rem2 = u % 136;                               \
                int colx = rem2 >> 1, seg = rem2 & 1;                          \
                src = xh + ((size_t)((p_lo + r) * 68 + colx)) * 512 + _c0 +    \
                      seg * 8;                                                 \
                dst = _xs + ((r * 68 + colx) * 24 + seg * 8) * 2;              \
            } else {                                                           \
                int v = u - 544;                                               \
                int ti = v >> 8, r8 = v & 255, co = r8 >> 1, seg = r8 & 1;     \
                src = g_whh + ((size_t)c_tapid[par][ti] * 256 + co0 + co) *    \
                          512 + _c0 + seg * 8;                                 \
                dst = _ws + ((ti * 128 + co) * 24 + seg * 8) * 2;              \
            }                                                                  \
            CP16(dst, src);                                                    \
        }                                                                      \
        CP_COMMIT();                                                           \
    } while (0)

    FILL_CHUNK(0, 0);

    for (int ci = 0; ci < 32; ci++) {
        CP_WAIT0();               // fill(ci) complete (fill(ci+1) not yet issued)
        __syncthreads();          // all warps done with compute(ci-1); data visible
        if (ci + 1 < 32) FILL_CHUNK(ci + 1, (ci + 1) & 1);   // other stage — safe

        const __half* xs = sm1 + (ci & 1) * STG_H;
        const __half* ws = xs + XS_H;

        for (int ti = 0; ti < ntap; ti++) {
            int coff = c_tdy[par][ti] * 68 + c_tdx[par][ti];
            uint32_t breg[4][2];
#pragma unroll
            for (int ni = 0; ni < 4; ni++) {
                const uint32_t* pB =
                    (const uint32_t*)&xs[(bcell[ni] + coff) * 24 + 2 * tig];
                breg[ni][0] = pB[0];
                breg[ni][1] = pB[4];
            }
#pragma unroll
            for (int mi = 0; mi < 4; mi++) {
                const uint32_t* pA = (const uint32_t*)
                    &ws[(ti * 128 + warp_m * 64 + mi * 16 + grp) * 24 + 2 * tig];
                uint32_t a0 = pA[0], a2 = pA[4];
                uint32_t a1 = pA[96], a3 = pA[100];
#pragma unroll
                for (int ni = 0; ni < 4; ni++)
                    mma16816(acc[mi][ni], a0, a1, a2, a3,
                             breg[ni][0], breg[ni][1]);
            }
        }
    }

    __half2* zpp = (__half2*)(g_z + ((size_t)(b * 4 + par)) * 2240 * 512);
#pragma unroll
    for (int mi = 0; mi < 4; mi++) {
        int coA = co0 + warp_m * 64 + mi * 16 + grp;
#pragma unroll
        for (int ni = 0; ni < 4; ni++) {
            int n = n0 + warp_n * 32 + ni * 8 + 2 * tig;   // even
            if (n < 4356) {
                size_t base = (size_t)(n >> 1) * 256;
                float* f = acc[mi][ni];
                zpp[base + coA] =
                    __halves2half2(__float2half_rn(f[0]), __float2half_rn(f[1]));
                zpp[base + coA + 8] =
                    __halves2half2(__float2half_rn(f[2]), __float2half_rn(f[3]));
            }
        }
    }
#undef FILL_CHUNK
}

// ---------------------------- stage2: FIR + epilogue -----------------------
// grid (64 = 8x8 tiles of 16x16 px, 8 co-groups of 32, 8 b), 256 threads.
// zt[400 cells][34] fp32 (54.4KB -> 4 CTAs/SM, even stride for float2 LDS).
// Fill: one uint32 word = z(n) and z(n+1) for one co -> 25 coalesced loads.
#define S2_SMEM (400 * 34 * 4)

__global__ __launch_bounds__(256) void stage2(const float* __restrict__ bias,
                                              const float* __restrict__ noise,
                                              const float* __restrict__ nstr,
                                              float* __restrict__ out) {
    extern __shared__ float zt[];      // [cell(4par x 10pl x 10q)][34]

    int bx = blockIdx.x;
    int my0 = (bx >> 3) * 16, mx0 = (bx & 7) * 16;
    int P0 = my0 >> 1, Q0 = mx0 >> 1;          // Q0 even
    int co0 = blockIdx.y * 32, b = blockIdx.z;
    int tid = threadIdx.x;

    // ---- fill zt: 200 pair-cells, thread strides 8; word co covers n & n+1
    {
        const uint32_t* zsrc32 =
            (const uint32_t*)(g_z + (size_t)(b * 4) * 2240 * 512);
        int co_l = tid & 31;
        int pc = tid >> 5;                      // 0..7
        int xp2 = pc, ys = 0, par = 0;
        if (xp2 >= 5) { xp2 -= 5; ys = 1; }
        int nh = (P0 + ys) * 33 + (Q0 >> 1) + xp2;   // (n>>1) of even n
        int cell = ys * 10 + 2 * xp2;                // + par*100 (par=0 here)
        int cow = co0 + co_l;
        for (int i = 0; i < 25; i++) {
            uint32_t v = zsrc32[((size_t)par * 2240 + nh) * 256 + cow];
            __half2 h2 = *(__half2*)&v;
            zt[cell * 34 + co_l] = __half2float(h2.x);          // n   (even)
            zt[(cell + 1) * 34 + co_l] = __half2float(h2.y);    // n+1 (odd)
            xp2 += 8; nh += 8; cell += 16;
            while (xp2 >= 5) { xp2 -= 5; ys++; nh += 28; }      // +33 row -5
            if (ys >= 10) { ys -= 10; par++; nh -= 330; }       // cell net 0
        }
    }
    __syncthreads();

    // ---- streaming separable FIR: float2 taps (both co at once)
    const float C4[4] = {0.25f, 0.75f, 0.75f, 0.25f};
    int px = tid & 15, cg = tid >> 4;
    int c0l = 2 * cg;                           // even -> float2 aligned

    int offk[4];
#pragma unroll
    for (int kx = 0; kx < 4; kx++) {
        int zxl = px + kx;
        offk[kx] = ((zxl & 1) * 100 + (zxl >> 1)) * 34 + c0l;   // even
    }

    float ns = *nstr;
    int coA = co0 + c0l;
    float bv0 = bias[coA], bv1 = bias[coA + 1];
    float* op0 = out + ((size_t)(b * 256 + coA) * 128 + my0) * 128 + mx0 + px;
    float* op1 = op0 + 16384;
    const float* np = noise + my0 * 128 + mx0 + px;

    float w0a = 0.f, w1a = 0.f, w2a = 0.f, w3a = 0.f;
    float w0b = 0.f, w1b = 0.f, w2b = 0.f, w3b = 0.f;

#pragma unroll
    for (int zyl = 0; zyl < 19; zyl++) {
        int base = (((zyl & 1) * 2) * 100 + (zyl >> 1) * 10) * 34;  // cexpr even
        float a0 = 0.f, a1 = 0.f;
#pragma unroll
        for (int kx = 0; kx < 4; kx++) {
            float2 v = *(const float2*)&zt[base + offk[kx]];
            a0 += C4[kx] * v.x;
            a1 += C4[kx] * v.y;
        }
        w0a = w1a; w1a = w2a; w2a = w3a; w3a = a0;
        w0b = w1b; w1b = w2b; w2b = w3b; w3b = a1;
        if (zyl >= 3) {
            int py = zyl - 3;
            float s0 = C4[0] * w0a + C4[1] * w1a + C4[2] * w2a + C4[3] * w3a;
            float s1 = C4[0] * w0b + C4[1] * w1b + C4[2] * w2b + C4[3] * w3b;
            float nz = np[py * 128] * ns;
            float v0 = s0 + nz + bv0;
            float v1 = s1 + nz + bv1;
            v0 = (v0 >= 0.f ? v0 : 0.2f * v0) * 1.41421356237309515f;
            v1 = (v1 >= 0.f ? v1 : 0.2f * v1) * 1.41421356237309515f;
            op0[py * 128] = v0;
            op1[py * 128] = v1;
        }
    }
}

// ---------------------------------------------------------------------------
extern "C" void kernel_launch(void* const* d_in, const int* in_sizes, int n_in,
                              void* d_out, int out_size) {
    (void)in_sizes; (void)n_in; (void)out_size;
    const float* x     = (const float*)d_in[0];   // [8,512,64,64]
    const float* w     = (const float*)d_in[1];   // [256,512,3,3]
    const float* bias  = (const float*)d_in[2];   // [256]
    const float* noise = (const float*)d_in[3];   // [128,128]
    const float* nstr  = (const float*)d_in[4];   // scalar
    float* out = (float*)d_out;                   // [8,256,128,128]

    cudaFuncSetAttribute(stage1, cudaFuncAttributeMaxDynamicSharedMemorySize,
                         S1_SMEM);
    cudaFuncSetAttribute(stage2, cudaFuncAttributeMaxDynamicSharedMemorySize,
                         S2_SMEM);

    prep_weights<<<256, 256>>>(w);
    dim3 gx(74, 8);
    prep_x<<<gx, 256>>>(x);

    dim3 g1(35, 8, 8);
    stage1<<<g1, 256, S1_SMEM>>>();

    dim3 g2(64, 8, 8);
    stage2<<<g2, 256, S2_SMEM>>>(bias, noise, nstr, out);
}